// round 1
// baseline (speedup 1.0000x reference)
#include <cuda_runtime.h>

#define HID 1024
#define NHEADS 16
#define DH 64
#define BATCH 4
#define SEQ 2048
#define MTOT (BATCH*SEQ)

// Scratch (static device allocations are allowed)
__device__ float g_Qp[MTOT*HID];
__device__ float g_Kp[MTOT*HID];
__device__ float g_Vp[MTOT*HID];
__device__ float g_Hb[MTOT*HID];

// ---------------------------------------------------------------------------
// NT GEMM with bias: C[m,n] = sum_k A[m,k]*W[n,k] + bias[n]
// Block tile 128x128, 256 threads, 8x8 per thread, K-step 8.
// blockIdx.z selects one of up to 3 (A,W,bias,C) sets (fused QKV).
// ---------------------------------------------------------------------------
__global__ __launch_bounds__(256) void gemm_nt_bias(
    const float* __restrict__ A0, const float* __restrict__ A1, const float* __restrict__ A2,
    const float* __restrict__ W0, const float* __restrict__ W1, const float* __restrict__ W2,
    const float* __restrict__ b0, const float* __restrict__ b1, const float* __restrict__ b2,
    float* __restrict__ C0, float* __restrict__ C1, float* __restrict__ C2,
    int Mdim, int Ndim, int Kdim)
{
    const int z = blockIdx.z;
    const float* A    = (z == 0) ? A0 : (z == 1) ? A1 : A2;
    const float* W    = (z == 0) ? W0 : (z == 1) ? W1 : W2;
    const float* bias = (z == 0) ? b0 : (z == 1) ? b1 : b2;
    float*       C    = (z == 0) ? C0 : (z == 1) ? C1 : C2;

    __shared__ float sA[8 * 132];
    __shared__ float sW[8 * 132];

    const int t  = threadIdx.x;
    const int tx = t & 15;
    const int ty = t >> 4;
    const int m0 = blockIdx.y * 128;
    const int n0 = blockIdx.x * 128;

    float acc[8][8];
#pragma unroll
    for (int i = 0; i < 8; i++)
#pragma unroll
        for (int j = 0; j < 8; j++) acc[i][j] = 0.0f;

    const int lm = t >> 1;          // 0..127
    const int lk = (t & 1) * 4;     // 0 or 4

    const float* Aptr = A + (long)(m0 + lm) * Kdim + lk;
    const float* Wptr = W + (long)(n0 + lm) * Kdim + lk;

    for (int k0 = 0; k0 < Kdim; k0 += 8) {
        float4 av = *(const float4*)(Aptr + k0);
        float4 wv = *(const float4*)(Wptr + k0);
        sA[(lk + 0) * 132 + lm] = av.x;
        sA[(lk + 1) * 132 + lm] = av.y;
        sA[(lk + 2) * 132 + lm] = av.z;
        sA[(lk + 3) * 132 + lm] = av.w;
        sW[(lk + 0) * 132 + lm] = wv.x;
        sW[(lk + 1) * 132 + lm] = wv.y;
        sW[(lk + 2) * 132 + lm] = wv.z;
        sW[(lk + 3) * 132 + lm] = wv.w;
        __syncthreads();

#pragma unroll
        for (int kk = 0; kk < 8; kk++) {
            float4 a0v = *(const float4*)&sA[kk * 132 + 8 * ty];
            float4 a1v = *(const float4*)&sA[kk * 132 + 8 * ty + 4];
            float4 w0v = *(const float4*)&sW[kk * 132 + 8 * tx];
            float4 w1v = *(const float4*)&sW[kk * 132 + 8 * tx + 4];
            float a[8] = {a0v.x, a0v.y, a0v.z, a0v.w, a1v.x, a1v.y, a1v.z, a1v.w};
            float b[8] = {w0v.x, w0v.y, w0v.z, w0v.w, w1v.x, w1v.y, w1v.z, w1v.w};
#pragma unroll
            for (int i = 0; i < 8; i++)
#pragma unroll
                for (int j = 0; j < 8; j++) acc[i][j] += a[i] * b[j];
        }
        __syncthreads();
    }

    // Epilogue: add bias, vectorized stores
    float4 bj0 = *(const float4*)&bias[n0 + 8 * tx];
    float4 bj1 = *(const float4*)&bias[n0 + 8 * tx + 4];
#pragma unroll
    for (int i = 0; i < 8; i++) {
        const long m = m0 + 8 * ty + i;
        float4 o0, o1;
        o0.x = acc[i][0] + bj0.x; o0.y = acc[i][1] + bj0.y;
        o0.z = acc[i][2] + bj0.z; o0.w = acc[i][3] + bj0.w;
        o1.x = acc[i][4] + bj1.x; o1.y = acc[i][5] + bj1.y;
        o1.z = acc[i][6] + bj1.z; o1.w = acc[i][7] + bj1.w;
        *(float4*)&C[m * Ndim + n0 + 8 * tx]     = o0;
        *(float4*)&C[m * Ndim + n0 + 8 * tx + 4] = o1;
    }
}

// ---------------------------------------------------------------------------
// Flash attention, fp32. Block: 64 query rows for one (b,h); loop 64-key tiles.
// 256 threads, thread (tx,ty): rows 4*ty..4*ty+3, cols tx+16*j (j=0..3).
// Query-row mask: masked rows get all scores = -1e9 -> exact uniform softmax,
// identical to the reference semantics.
// ---------------------------------------------------------------------------
__global__ __launch_bounds__(256) void flash_attn(
    const float* __restrict__ Qp, const float* __restrict__ Kp,
    const float* __restrict__ Vp, const int* __restrict__ mask,
    float* __restrict__ Hout)
{
    extern __shared__ float sm[];
    float* qs = sm;                 // [64][68]
    float* ks = sm + 64 * 68;       // [64][68]
    float* vs = sm + 2 * 64 * 68;   // [64][68]
    float* ps = sm + 3 * 64 * 68;   // [64][68]

    const int t  = threadIdx.x;
    const int tx = t & 15;
    const int ty = t >> 4;
    const int bh = blockIdx.y;
    const int b  = bh >> 4;
    const int h  = bh & 15;
    const int q0 = blockIdx.x * 64;
    const float scale = 0.125f; // 1/sqrt(64)

    // Load Q tile (64 rows x 64 cols of the head slice)
#pragma unroll
    for (int ii = 0; ii < 4; ii++) {
        int f4 = t + 256 * ii;      // 0..1023
        int r  = f4 >> 4;
        int c4 = f4 & 15;
        float4 v = *(const float4*)(Qp + (long)(b * SEQ + q0 + r) * HID + h * DH + c4 * 4);
        *(float4*)&qs[r * 68 + c4 * 4] = v;
    }

    int mrow[4];
#pragma unroll
    for (int i = 0; i < 4; i++) mrow[i] = mask[b * SEQ + q0 + 4 * ty + i];

    float m_i[4], l_i[4], o[4][4];
#pragma unroll
    for (int i = 0; i < 4; i++) {
        m_i[i] = -1e30f;
        l_i[i] = 0.0f;
#pragma unroll
        for (int j = 0; j < 4; j++) o[i][j] = 0.0f;
    }

    for (int kt = 0; kt < SEQ; kt += 64) {
        // Load K and V tiles
#pragma unroll
        for (int ii = 0; ii < 4; ii++) {
            int f4 = t + 256 * ii;
            int r  = f4 >> 4;
            int c4 = f4 & 15;
            long base = (long)(b * SEQ + kt + r) * HID + h * DH + c4 * 4;
            *(float4*)&ks[r * 68 + c4 * 4] = *(const float4*)(Kp + base);
            *(float4*)&vs[r * 68 + c4 * 4] = *(const float4*)(Vp + base);
        }
        __syncthreads();

        // S = Q @ K^T
        float s[4][4];
#pragma unroll
        for (int i = 0; i < 4; i++)
#pragma unroll
            for (int j = 0; j < 4; j++) s[i][j] = 0.0f;

#pragma unroll
        for (int d4 = 0; d4 < 16; d4++) {
            float4 a[4], bb[4];
#pragma unroll
            for (int i = 0; i < 4; i++)
                a[i] = *(const float4*)&qs[(4 * ty + i) * 68 + d4 * 4];
#pragma unroll
            for (int j = 0; j < 4; j++)
                bb[j] = *(const float4*)&ks[(tx + 16 * j) * 68 + d4 * 4];
#pragma unroll
            for (int i = 0; i < 4; i++)
#pragma unroll
                for (int j = 0; j < 4; j++)
                    s[i][j] += a[i].x * bb[j].x + a[i].y * bb[j].y
                             + a[i].z * bb[j].z + a[i].w * bb[j].w;
        }

        // scale + query-row mask
#pragma unroll
        for (int i = 0; i < 4; i++)
#pragma unroll
            for (int j = 0; j < 4; j++)
                s[i][j] = mrow[i] ? s[i][j] * scale : -1e9f;

        // Online softmax (per-row, reduced across the 16 tx lanes)
#pragma unroll
        for (int i = 0; i < 4; i++) {
            float mx = s[i][0];
#pragma unroll
            for (int j = 1; j < 4; j++) mx = fmaxf(mx, s[i][j]);
#pragma unroll
            for (int off = 8; off >= 1; off >>= 1)
                mx = fmaxf(mx, __shfl_xor_sync(0xffffffffu, mx, off, 16));
            float mn   = fmaxf(m_i[i], mx);
            float corr = __expf(m_i[i] - mn);
            m_i[i] = mn;
            float rs = 0.0f;
#pragma unroll
            for (int j = 0; j < 4; j++) {
                float p = __expf(s[i][j] - mn);
                s[i][j] = p;
                rs += p;
            }
#pragma unroll
            for (int off = 8; off >= 1; off >>= 1)
                rs += __shfl_xor_sync(0xffffffffu, rs, off, 16);
            l_i[i] = l_i[i] * corr + rs;
#pragma unroll
            for (int j = 0; j < 4; j++) o[i][j] *= corr;
        }

        // Stage P to smem
#pragma unroll
        for (int i = 0; i < 4; i++)
#pragma unroll
            for (int j = 0; j < 4; j++)
                ps[(4 * ty + i) * 68 + tx + 16 * j] = s[i][j];
        __syncthreads();

        // O += P @ V
#pragma unroll
        for (int k4 = 0; k4 < 16; k4++) {
            float4 pv[4];
#pragma unroll
            for (int i = 0; i < 4; i++)
                pv[i] = *(const float4*)&ps[(4 * ty + i) * 68 + k4 * 4];
#pragma unroll
            for (int kk = 0; kk < 4; kk++) {
                float bb[4];
#pragma unroll
                for (int j = 0; j < 4; j++)
                    bb[j] = vs[(k4 * 4 + kk) * 68 + tx + 16 * j];
                float pa[4];
                pa[0] = (kk == 0) ? pv[0].x : (kk == 1) ? pv[0].y : (kk == 2) ? pv[0].z : pv[0].w;
                pa[1] = (kk == 0) ? pv[1].x : (kk == 1) ? pv[1].y : (kk == 2) ? pv[1].z : pv[1].w;
                pa[2] = (kk == 0) ? pv[2].x : (kk == 1) ? pv[2].y : (kk == 2) ? pv[2].z : pv[2].w;
                pa[3] = (kk == 0) ? pv[3].x : (kk == 1) ? pv[3].y : (kk == 2) ? pv[3].z : pv[3].w;
#pragma unroll
                for (int i = 0; i < 4; i++)
#pragma unroll
                    for (int j = 0; j < 4; j++) o[i][j] += pa[i] * bb[j];
            }
        }
        __syncthreads();
    }

    // Normalize and write out in [B,S,H*dh] layout
#pragma unroll
    for (int i = 0; i < 4; i++) {
        float inv = 1.0f / l_i[i];
#pragma unroll
        for (int j = 0; j < 4; j++)
            Hout[(long)(b * SEQ + q0 + 4 * ty + i) * HID + h * DH + tx + 16 * j] = o[i][j] * inv;
    }
}

// ---------------------------------------------------------------------------

extern "C" void kernel_launch(void* const* d_in, const int* in_sizes, int n_in,
                              void* d_out, int out_size)
{
    const float* q    = (const float*)d_in[0];
    const float* k    = (const float*)d_in[1];
    const float* v    = (const float*)d_in[2];
    const int*   mask = (const int*)  d_in[3];
    const float* wq   = (const float*)d_in[4];
    const float* bq   = (const float*)d_in[5];
    const float* wk   = (const float*)d_in[6];
    const float* bk   = (const float*)d_in[7];
    const float* wv   = (const float*)d_in[8];
    const float* bv   = (const float*)d_in[9];
    const float* wo   = (const float*)d_in[10];
    const float* bo   = (const float*)d_in[11];
    float* out = (float*)d_out;

    float *Qp, *Kp, *Vp, *Hb;
    cudaGetSymbolAddress((void**)&Qp, g_Qp);
    cudaGetSymbolAddress((void**)&Kp, g_Kp);
    cudaGetSymbolAddress((void**)&Vp, g_Vp);
    cudaGetSymbolAddress((void**)&Hb, g_Hb);

    const int smem_flash = 4 * 64 * 68 * (int)sizeof(float); // 69632 B
    cudaFuncSetAttribute(flash_attn, cudaFuncAttributeMaxDynamicSharedMemorySize, smem_flash);

    // 1. Fused QKV projections
    dim3 gQKV(HID / 128, MTOT / 128, 3);
    gemm_nt_bias<<<gQKV, 256>>>(q, k, v, wq, wk, wv, bq, bk, bv, Qp, Kp, Vp,
                                MTOT, HID, HID);

    // 2. Flash attention
    dim3 gF(SEQ / 64, BATCH * NHEADS);
    flash_attn<<<gF, 256, smem_flash>>>(Qp, Kp, Vp, mask, Hb);

    // 3. Output projection
    dim3 gO(HID / 128, MTOT / 128, 1);
    gemm_nt_bias<<<gO, 256>>>(Hb, Hb, Hb, wo, wo, wo, bo, bo, bo, out, out, out,
                              MTOT, HID, HID);
}

// round 2
// speedup vs baseline: 1.0009x; 1.0009x over previous
#include <cuda_runtime.h>

#define HID 1024
#define NHEADS 16
#define DH 64
#define BATCH 4
#define SEQ 2048
#define MTOT (BATCH*SEQ)

// Scratch (static device allocations are allowed)
__device__ float g_Qp[MTOT*HID];
__device__ float g_Kp[MTOT*HID];
__device__ float g_Vp[MTOT*HID];
__device__ float g_Hb[MTOT*HID];

// ---------------------------------------------------------------------------
// NT GEMM with bias: C[m,n] = sum_k A[m,k]*W[n,k] + bias[n]
// Block tile 128x128, 256 threads, 8x8 per thread, K-step 8.
// blockIdx.z selects one of up to 3 (A,W,bias,C) sets (fused QKV).
// ---------------------------------------------------------------------------
__global__ __launch_bounds__(256) void gemm_nt_bias(
    const float* __restrict__ A0, const float* __restrict__ A1, const float* __restrict__ A2,
    const float* __restrict__ W0, const float* __restrict__ W1, const float* __restrict__ W2,
    const float* __restrict__ b0, const float* __restrict__ b1, const float* __restrict__ b2,
    float* __restrict__ C0, float* __restrict__ C1, float* __restrict__ C2,
    int Mdim, int Ndim, int Kdim)
{
    const int z = blockIdx.z;
    const float* A    = (z == 0) ? A0 : (z == 1) ? A1 : A2;
    const float* W    = (z == 0) ? W0 : (z == 1) ? W1 : W2;
    const float* bias = (z == 0) ? b0 : (z == 1) ? b1 : b2;
    float*       C    = (z == 0) ? C0 : (z == 1) ? C1 : C2;

    __shared__ float sA[8 * 132];
    __shared__ float sW[8 * 132];

    const int t  = threadIdx.x;
    const int tx = t & 15;
    const int ty = t >> 4;
    const int m0 = blockIdx.y * 128;
    const int n0 = blockIdx.x * 128;

    float acc[8][8];
#pragma unroll
    for (int i = 0; i < 8; i++)
#pragma unroll
        for (int j = 0; j < 8; j++) acc[i][j] = 0.0f;

    const int lm = t >> 1;          // 0..127
    const int lk = (t & 1) * 4;     // 0 or 4

    const float* Aptr = A + (long)(m0 + lm) * Kdim + lk;
    const float* Wptr = W + (long)(n0 + lm) * Kdim + lk;

    for (int k0 = 0; k0 < Kdim; k0 += 8) {
        float4 av = *(const float4*)(Aptr + k0);
        float4 wv = *(const float4*)(Wptr + k0);
        sA[(lk + 0) * 132 + lm] = av.x;
        sA[(lk + 1) * 132 + lm] = av.y;
        sA[(lk + 2) * 132 + lm] = av.z;
        sA[(lk + 3) * 132 + lm] = av.w;
        sW[(lk + 0) * 132 + lm] = wv.x;
        sW[(lk + 1) * 132 + lm] = wv.y;
        sW[(lk + 2) * 132 + lm] = wv.z;
        sW[(lk + 3) * 132 + lm] = wv.w;
        __syncthreads();

#pragma unroll
        for (int kk = 0; kk < 8; kk++) {
            float4 a0v = *(const float4*)&sA[kk * 132 + 8 * ty];
            float4 a1v = *(const float4*)&sA[kk * 132 + 8 * ty + 4];
            float4 w0v = *(const float4*)&sW[kk * 132 + 8 * tx];
            float4 w1v = *(const float4*)&sW[kk * 132 + 8 * tx + 4];
            float a[8] = {a0v.x, a0v.y, a0v.z, a0v.w, a1v.x, a1v.y, a1v.z, a1v.w};
            float b[8] = {w0v.x, w0v.y, w0v.z, w0v.w, w1v.x, w1v.y, w1v.z, w1v.w};
#pragma unroll
            for (int i = 0; i < 8; i++)
#pragma unroll
                for (int j = 0; j < 8; j++) acc[i][j] += a[i] * b[j];
        }
        __syncthreads();
    }

    // Epilogue: add bias, vectorized stores
    float4 bj0 = *(const float4*)&bias[n0 + 8 * tx];
    float4 bj1 = *(const float4*)&bias[n0 + 8 * tx + 4];
#pragma unroll
    for (int i = 0; i < 8; i++) {
        const long m = m0 + 8 * ty + i;
        float4 o0, o1;
        o0.x = acc[i][0] + bj0.x; o0.y = acc[i][1] + bj0.y;
        o0.z = acc[i][2] + bj0.z; o0.w = acc[i][3] + bj0.w;
        o1.x = acc[i][4] + bj1.x; o1.y = acc[i][5] + bj1.y;
        o1.z = acc[i][6] + bj1.z; o1.w = acc[i][7] + bj1.w;
        *(float4*)&C[m * Ndim + n0 + 8 * tx]     = o0;
        *(float4*)&C[m * Ndim + n0 + 8 * tx + 4] = o1;
    }
}

// ---------------------------------------------------------------------------
// Flash attention, fp32. Block: 64 query rows for one (b,h); loop 64-key tiles.
// 256 threads, thread (tx,ty): rows 4*ty..4*ty+3, cols tx+16*j (j=0..3).
// Query-row mask: masked rows get all scores = -1e9 -> exact uniform softmax,
// identical to the reference semantics.
// ---------------------------------------------------------------------------
__global__ __launch_bounds__(256) void flash_attn(
    const float* __restrict__ Qp, const float* __restrict__ Kp,
    const float* __restrict__ Vp, const int* __restrict__ mask,
    float* __restrict__ Hout)
{
    extern __shared__ float sm[];
    float* qs = sm;                 // [64][68]
    float* ks = sm + 64 * 68;       // [64][68]
    float* vs = sm + 2 * 64 * 68;   // [64][68]
    float* ps = sm + 3 * 64 * 68;   // [64][68]

    const int t  = threadIdx.x;
    const int tx = t & 15;
    const int ty = t >> 4;
    const int bh = blockIdx.y;
    const int b  = bh >> 4;
    const int h  = bh & 15;
    const int q0 = blockIdx.x * 64;
    const float scale = 0.125f; // 1/sqrt(64)

    // Load Q tile (64 rows x 64 cols of the head slice)
#pragma unroll
    for (int ii = 0; ii < 4; ii++) {
        int f4 = t + 256 * ii;      // 0..1023
        int r  = f4 >> 4;
        int c4 = f4 & 15;
        float4 v = *(const float4*)(Qp + (long)(b * SEQ + q0 + r) * HID + h * DH + c4 * 4);
        *(float4*)&qs[r * 68 + c4 * 4] = v;
    }

    int mrow[4];
#pragma unroll
    for (int i = 0; i < 4; i++) mrow[i] = mask[b * SEQ + q0 + 4 * ty + i];

    float m_i[4], l_i[4], o[4][4];
#pragma unroll
    for (int i = 0; i < 4; i++) {
        m_i[i] = -1e30f;
        l_i[i] = 0.0f;
#pragma unroll
        for (int j = 0; j < 4; j++) o[i][j] = 0.0f;
    }

    for (int kt = 0; kt < SEQ; kt += 64) {
        // Load K and V tiles
#pragma unroll
        for (int ii = 0; ii < 4; ii++) {
            int f4 = t + 256 * ii;
            int r  = f4 >> 4;
            int c4 = f4 & 15;
            long base = (long)(b * SEQ + kt + r) * HID + h * DH + c4 * 4;
            *(float4*)&ks[r * 68 + c4 * 4] = *(const float4*)(Kp + base);
            *(float4*)&vs[r * 68 + c4 * 4] = *(const float4*)(Vp + base);
        }
        __syncthreads();

        // S = Q @ K^T
        float s[4][4];
#pragma unroll
        for (int i = 0; i < 4; i++)
#pragma unroll
            for (int j = 0; j < 4; j++) s[i][j] = 0.0f;

#pragma unroll
        for (int d4 = 0; d4 < 16; d4++) {
            float4 a[4], bb[4];
#pragma unroll
            for (int i = 0; i < 4; i++)
                a[i] = *(const float4*)&qs[(4 * ty + i) * 68 + d4 * 4];
#pragma unroll
            for (int j = 0; j < 4; j++)
                bb[j] = *(const float4*)&ks[(tx + 16 * j) * 68 + d4 * 4];
#pragma unroll
            for (int i = 0; i < 4; i++)
#pragma unroll
                for (int j = 0; j < 4; j++)
                    s[i][j] += a[i].x * bb[j].x + a[i].y * bb[j].y
                             + a[i].z * bb[j].z + a[i].w * bb[j].w;
        }

        // scale + query-row mask
#pragma unroll
        for (int i = 0; i < 4; i++)
#pragma unroll
            for (int j = 0; j < 4; j++)
                s[i][j] = mrow[i] ? s[i][j] * scale : -1e9f;

        // Online softmax (per-row, reduced across the 16 tx lanes)
#pragma unroll
        for (int i = 0; i < 4; i++) {
            float mx = s[i][0];
#pragma unroll
            for (int j = 1; j < 4; j++) mx = fmaxf(mx, s[i][j]);
#pragma unroll
            for (int off = 8; off >= 1; off >>= 1)
                mx = fmaxf(mx, __shfl_xor_sync(0xffffffffu, mx, off, 16));
            float mn   = fmaxf(m_i[i], mx);
            float corr = __expf(m_i[i] - mn);
            m_i[i] = mn;
            float rs = 0.0f;
#pragma unroll
            for (int j = 0; j < 4; j++) {
                float p = __expf(s[i][j] - mn);
                s[i][j] = p;
                rs += p;
            }
#pragma unroll
            for (int off = 8; off >= 1; off >>= 1)
                rs += __shfl_xor_sync(0xffffffffu, rs, off, 16);
            l_i[i] = l_i[i] * corr + rs;
#pragma unroll
            for (int j = 0; j < 4; j++) o[i][j] *= corr;
        }

        // Stage P to smem
#pragma unroll
        for (int i = 0; i < 4; i++)
#pragma unroll
            for (int j = 0; j < 4; j++)
                ps[(4 * ty + i) * 68 + tx + 16 * j] = s[i][j];
        __syncthreads();

        // O += P @ V
#pragma unroll
        for (int k4 = 0; k4 < 16; k4++) {
            float4 pv[4];
#pragma unroll
            for (int i = 0; i < 4; i++)
                pv[i] = *(const float4*)&ps[(4 * ty + i) * 68 + k4 * 4];
#pragma unroll
            for (int kk = 0; kk < 4; kk++) {
                float bb[4];
#pragma unroll
                for (int j = 0; j < 4; j++)
                    bb[j] = vs[(k4 * 4 + kk) * 68 + tx + 16 * j];
                float pa[4];
                pa[0] = (kk == 0) ? pv[0].x : (kk == 1) ? pv[0].y : (kk == 2) ? pv[0].z : pv[0].w;
                pa[1] = (kk == 0) ? pv[1].x : (kk == 1) ? pv[1].y : (kk == 2) ? pv[1].z : pv[1].w;
                pa[2] = (kk == 0) ? pv[2].x : (kk == 1) ? pv[2].y : (kk == 2) ? pv[2].z : pv[2].w;
                pa[3] = (kk == 0) ? pv[3].x : (kk == 1) ? pv[3].y : (kk == 2) ? pv[3].z : pv[3].w;
#pragma unroll
                for (int i = 0; i < 4; i++)
#pragma unroll
                    for (int j = 0; j < 4; j++) o[i][j] += pa[i] * bb[j];
            }
        }
        __syncthreads();
    }

    // Normalize and write out in [B,S,H*dh] layout
#pragma unroll
    for (int i = 0; i < 4; i++) {
        float inv = 1.0f / l_i[i];
#pragma unroll
        for (int j = 0; j < 4; j++)
            Hout[(long)(b * SEQ + q0 + 4 * ty + i) * HID + h * DH + tx + 16 * j] = o[i][j] * inv;
    }
}

// ---------------------------------------------------------------------------

extern "C" void kernel_launch(void* const* d_in, const int* in_sizes, int n_in,
                              void* d_out, int out_size)
{
    const float* q    = (const float*)d_in[0];
    const float* k    = (const float*)d_in[1];
    const float* v    = (const float*)d_in[2];
    const int*   mask = (const int*)  d_in[3];
    const float* wq   = (const float*)d_in[4];
    const float* bq   = (const float*)d_in[5];
    const float* wk   = (const float*)d_in[6];
    const float* bk   = (const float*)d_in[7];
    const float* wv   = (const float*)d_in[8];
    const float* bv   = (const float*)d_in[9];
    const float* wo   = (const float*)d_in[10];
    const float* bo   = (const float*)d_in[11];
    float* out = (float*)d_out;

    float *Qp, *Kp, *Vp, *Hb;
    cudaGetSymbolAddress((void**)&Qp, g_Qp);
    cudaGetSymbolAddress((void**)&Kp, g_Kp);
    cudaGetSymbolAddress((void**)&Vp, g_Vp);
    cudaGetSymbolAddress((void**)&Hb, g_Hb);

    const int smem_flash = 4 * 64 * 68 * (int)sizeof(float); // 69632 B
    cudaFuncSetAttribute(flash_attn, cudaFuncAttributeMaxDynamicSharedMemorySize, smem_flash);

    // 1. Fused QKV projections
    dim3 gQKV(HID / 128, MTOT / 128, 3);
    gemm_nt_bias<<<gQKV, 256>>>(q, k, v, wq, wk, wv, bq, bk, bv, Qp, Kp, Vp,
                                MTOT, HID, HID);

    // 2. Flash attention
    dim3 gF(SEQ / 64, BATCH * NHEADS);
    flash_attn<<<gF, 256, smem_flash>>>(Qp, Kp, Vp, mask, Hb);

    // 3. Output projection
    dim3 gO(HID / 128, MTOT / 128, 1);
    gemm_nt_bias<<<gO, 256>>>(Hb, Hb, Hb, wo, wo, wo, bo, bo, bo, out, out, out,
                              MTOT, HID, HID);
}

// round 4
// speedup vs baseline: 2.5504x; 2.5480x over previous
#include <cuda_runtime.h>
#include <cstdint>

#define HID 1024
#define SEQ 2048
#define BATCH 4
#define NHEADS 16
#define DH 64
#define MTOT (BATCH*SEQ)

// ---------------- scratch (static device arrays are allowed) ---------------
__device__ float g_qr[MTOT*HID];
__device__ float g_kr[MTOT*HID];
__device__ float g_vr[MTOT*HID];
__device__ float g_wqr[HID*HID];
__device__ float g_wkr[HID*HID];
__device__ float g_wvr[HID*HID];
__device__ float g_wor[HID*HID];
__device__ float g_Qp[MTOT*HID];
__device__ float g_Kp[MTOT*HID];
__device__ float g_Vt[BATCH*NHEADS*DH*SEQ];   // [b,h,d,s]
__device__ float g_Hb[MTOT*HID];

// ---------------- helpers ---------------------------------------------------
__device__ __forceinline__ uint32_t smem_u32(const void* p){
    uint32_t a;
    asm("{ .reg .u64 t; cvta.to.shared.u64 t, %1; cvt.u32.u64 %0, t; }":"=r"(a):"l"(p));
    return a;
}
__device__ __forceinline__ uint32_t f2tf32(float x){
    uint32_t r; asm("cvt.rna.tf32.f32 %0, %1;":"=r"(r):"f"(x)); return r;
}
__device__ __forceinline__ float tf32r(float x){ return __uint_as_float(f2tf32(x)); }
__device__ __forceinline__ void cp16(const void* dst, const void* src){
    asm volatile("cp.async.cg.shared.global [%0], [%1], 16;"
                 ::"r"(smem_u32(dst)),"l"(src));
}
#define CP_COMMIT() asm volatile("cp.async.commit_group;":::"memory")
#define CP_WAIT1()  asm volatile("cp.async.wait_group 1;":::"memory")
#define CP_WAIT0()  asm volatile("cp.async.wait_group 0;":::"memory")

// mma.sync m16n8k8 tf32 (sm_80+, legal on plain sm_103 target)
__device__ __forceinline__ void mma8(float* d, const uint32_t* a, const uint32_t* b){
    asm volatile(
        "mma.sync.aligned.m16n8k8.row.col.f32.tf32.tf32.f32 "
        "{%0,%1,%2,%3}, {%4,%5,%6,%7}, {%8,%9}, {%0,%1,%2,%3};"
        : "+f"(d[0]),"+f"(d[1]),"+f"(d[2]),"+f"(d[3])
        : "r"(a[0]),"r"(a[1]),"r"(a[2]),"r"(a[3]),
          "r"(b[0]),"r"(b[1]));
}

// ---------------- pre-round fp32 -> tf32(RNE) -------------------------------
__global__ void round_k(const float* __restrict__ s, float* __restrict__ d, int n4){
    int i = blockIdx.x*256 + threadIdx.x;
    if(i < n4){
        float4 v = ((const float4*)s)[i];
        uint4 o;
        o.x=f2tf32(v.x); o.y=f2tf32(v.y); o.z=f2tf32(v.z); o.w=f2tf32(v.w);
        ((uint4*)d)[i]=o;
    }
}

// ---------------- warp-MMA GEMM: C = A @ W^T + bias -------------------------
// Block 128x128, 8 warps (4x2), warp tile 32x64. K chunks of 32, double buffer.
// modes: 0=Q(bias,*0.125,round) 1=K(round) 2=V(round+per-head transpose) 3=plain
#define GW_SMEM (4*128*36*4)
__global__ __launch_bounds__(256,1) void gemm_ws(
    const float* __restrict__ A0, const float* __restrict__ A1, const float* __restrict__ A2,
    const float* __restrict__ W0, const float* __restrict__ W1, const float* __restrict__ W2,
    const float* __restrict__ b0, const float* __restrict__ b1, const float* __restrict__ b2,
    float* __restrict__ C0, float* __restrict__ C1, float* __restrict__ C2,
    int mode_in)
{
    extern __shared__ float sm[];
    const int z = blockIdx.z;
    const float* A    = (z==0)?A0:(z==1)?A1:A2;
    const float* W    = (z==0)?W0:(z==1)?W1:W2;
    const float* bias = (z==0)?b0:(z==1)?b1:b2;
    float*       C    = (z==0)?C0:(z==1)?C1:C2;
    const int mode = (mode_in < 0) ? z : mode_in;

    float* As[2] = { sm,            sm + 128*36 };
    float* Ws[2] = { sm + 2*128*36, sm + 3*128*36 };

    const int t    = threadIdx.x;
    const int w    = t >> 5;
    const int lane = t & 31;
    const int g    = lane >> 2;      // groupID
    const int tig  = lane & 3;       // thread-in-group
    const int wm   = (w >> 1) * 32;  // warp M offset
    const int wn   = (w & 1) * 64;   // warp N offset
    const int m0   = blockIdx.y * 128;
    const int n0   = blockIdx.x * 128;

    float acc[2][8][4];
#pragma unroll
    for(int mt=0;mt<2;mt++)
#pragma unroll
        for(int nt=0;nt<8;nt++)
#pragma unroll
            for(int i2=0;i2<4;i2++) acc[mt][nt][i2]=0.f;

    // prologue: chunk 0
#pragma unroll
    for(int i=0;i<4;i++){
        int s = t + 256*i; int r = s>>3, c4 = s&7;
        cp16(&As[0][r*36 + c4*4], A + (size_t)(m0+r)*HID + c4*4);
        cp16(&Ws[0][r*36 + c4*4], W + (size_t)(n0+r)*HID + c4*4);
    }
    CP_COMMIT();

    for(int c=0;c<32;c++){
        const int buf = c & 1;
        if(c+1 < 32){
            const int k0 = (c+1)*32, nb = (c+1)&1;
#pragma unroll
            for(int i=0;i<4;i++){
                int s = t + 256*i; int r = s>>3, c4 = s&7;
                cp16(&As[nb][r*36 + c4*4], A + (size_t)(m0+r)*HID + k0 + c4*4);
                cp16(&Ws[nb][r*36 + c4*4], W + (size_t)(n0+r)*HID + k0 + c4*4);
            }
            CP_COMMIT();
            CP_WAIT1();
        } else {
            CP_WAIT0();
        }
        __syncthreads();

#pragma unroll
        for(int k8=0;k8<4;k8++){
            const int kk = k8*8;
            uint32_t a[2][4], b[8][2];
#pragma unroll
            for(int mt=0;mt<2;mt++){
                const float* ar  = &As[buf][(wm + mt*16 + g)*36 + kk];
                const float* ar8 = ar + 8*36;
                a[mt][0] = __float_as_uint(ar[tig]);
                a[mt][1] = __float_as_uint(ar8[tig]);
                a[mt][2] = __float_as_uint(ar[tig+4]);
                a[mt][3] = __float_as_uint(ar8[tig+4]);
            }
#pragma unroll
            for(int nt=0;nt<8;nt++){
                const float* br = &Ws[buf][(wn + nt*8 + g)*36 + kk];
                b[nt][0] = __float_as_uint(br[tig]);
                b[nt][1] = __float_as_uint(br[tig+4]);
            }
#pragma unroll
            for(int mt=0;mt<2;mt++)
#pragma unroll
                for(int nt=0;nt<8;nt++)
                    mma8(acc[mt][nt], a[mt], b[nt]);
        }
        __syncthreads();
    }

    // epilogue
#pragma unroll
    for(int mt=0;mt<2;mt++){
        const int row0 = m0 + wm + mt*16 + g;
        const int row1 = row0 + 8;
#pragma unroll
        for(int nt=0;nt<8;nt++){
            const int col0 = n0 + wn + nt*8 + 2*tig;
            const float bb0 = bias[col0], bb1 = bias[col0+1];
            float v00 = acc[mt][nt][0] + bb0, v01 = acc[mt][nt][1] + bb1;
            float v10 = acc[mt][nt][2] + bb0, v11 = acc[mt][nt][3] + bb1;
            if(mode==0){ v00*=0.125f; v01*=0.125f; v10*=0.125f; v11*=0.125f; }
            if(mode==2){
                // Vt[((b*16+h)*64+d)*SEQ + s], h=col>>6, d=col&63
                const int bb = row0 >> 11;
                const int s0 = row0 & 2047, s1 = row1 & 2047;
                const int h0 = col0 >> 6,  d0 = col0 & 63;
                const int h1 = (col0+1) >> 6, d1 = (col0+1) & 63;
                C[((size_t)(bb*NHEADS+h0)*DH + d0)*SEQ + s0] = tf32r(v00);
                C[((size_t)(bb*NHEADS+h1)*DH + d1)*SEQ + s0] = tf32r(v01);
                C[((size_t)(bb*NHEADS+h0)*DH + d0)*SEQ + s1] = tf32r(v10);
                C[((size_t)(bb*NHEADS+h1)*DH + d1)*SEQ + s1] = tf32r(v11);
            } else if(mode==3){
                *(float2*)&C[(size_t)row0*HID + col0] = make_float2(v00, v01);
                *(float2*)&C[(size_t)row1*HID + col0] = make_float2(v10, v11);
            } else {
                *(float2*)&C[(size_t)row0*HID + col0] = make_float2(tf32r(v00), tf32r(v01));
                *(float2*)&C[(size_t)row1*HID + col0] = make_float2(tf32r(v10), tf32r(v11));
            }
        }
    }
}

// ---------------- warp-MMA attention ---------------------------------------
// CTA = one (b,h) x 128 queries; 8 warps x 16 rows. 128-key tiles.
#define AW_SMEM ((128*68 + 128*68 + 64*132 + 128*132)*4)
__global__ __launch_bounds__(256,1) void attn_ws(
    const float* __restrict__ Qp, const float* __restrict__ Kp,
    const float* __restrict__ Vt, const int* __restrict__ mask,
    float* __restrict__ Hb)
{
    extern __shared__ float sm[];
    float* Qs = sm;                       // [128][68]
    float* Ks = Qs + 128*68;              // [128][68]
    float* Vs = Ks + 128*68;              // [64][132]  (V^T: [d][key])
    float* Ps = Vs + 64*132;              // [128][132]

    const int t    = threadIdx.x;
    const int w    = t >> 5;
    const int lane = t & 31;
    const int g    = lane >> 2;
    const int tig  = lane & 3;
    const int bh = blockIdx.y;
    const int b  = bh >> 4, h = bh & 15;
    const int q0 = blockIdx.x * 128;

    // load Q tile
#pragma unroll
    for(int i=0;i<8;i++){
        int s = t + 256*i; int r = s>>4, c4 = s&15;
        cp16(&Qs[r*68 + c4*4], Qp + (size_t)(b*SEQ + q0 + r)*HID + h*DH + c4*4);
    }
    CP_COMMIT(); CP_WAIT0();
    __syncthreads();

    // Q fragments held in registers (k = 64 -> 8 k-steps)
    uint32_t aq[8][4];
#pragma unroll
    for(int k8=0;k8<8;k8++){
        const float* qr  = &Qs[(w*16 + g)*68 + k8*8];
        const float* qr8 = qr + 8*68;
        aq[k8][0] = __float_as_uint(qr[tig]);
        aq[k8][1] = __float_as_uint(qr8[tig]);
        aq[k8][2] = __float_as_uint(qr[tig+4]);
        aq[k8][3] = __float_as_uint(qr8[tig+4]);
    }
    __syncthreads();

    const int row0g = q0 + w*16 + g;
    const int m0v = mask[b*SEQ + row0g];
    const int m1v = mask[b*SEQ + row0g + 8];

    float o[8][4];
#pragma unroll
    for(int nt=0;nt<8;nt++)
#pragma unroll
        for(int i2=0;i2<4;i2++) o[nt][i2]=0.f;
    float lsum0 = 0.f, lsum1 = 0.f;

    for(int kt=0; kt<16; kt++){
        // load K (128x64) and V^T (64x128) tiles
#pragma unroll
        for(int i=0;i<8;i++){
            int s = t + 256*i; int r = s>>4, c4 = s&15;
            cp16(&Ks[r*68 + c4*4], Kp + (size_t)(b*SEQ + kt*128 + r)*HID + h*DH + c4*4);
        }
#pragma unroll
        for(int i=0;i<8;i++){
            int s = t + 256*i; int d = s>>5, c4 = s&31;
            cp16(&Vs[d*132 + c4*4], Vt + ((size_t)(b*NHEADS+h)*DH + d)*SEQ + kt*128 + c4*4);
        }
        CP_COMMIT(); CP_WAIT0();
        __syncthreads();

        // S = Q @ K^T  (Q carries 1/8 scale); warp computes 16x128
        float s4[16][4];
#pragma unroll
        for(int nt=0;nt<16;nt++)
#pragma unroll
            for(int i2=0;i2<4;i2++) s4[nt][i2]=0.f;
#pragma unroll
        for(int k8=0;k8<8;k8++){
#pragma unroll
            for(int nt=0;nt<16;nt++){
                const float* br = &Ks[(nt*8 + g)*68 + k8*8];
                uint32_t bb[2] = { __float_as_uint(br[tig]), __float_as_uint(br[tig+4]) };
                mma8(s4[nt], aq[k8], bb);
            }
        }

        // P = exp(S) (masked rows -> 1), accumulate row sums, stage to smem
        float* pr0 = &Ps[(w*16 + g)*132];
        float* pr1 = pr0 + 8*132;
#pragma unroll
        for(int nt=0;nt<16;nt++){
            const int cc = nt*8 + 2*tig;
            float p00, p01, p10, p11;
            if(m0v){ p00 = __expf(s4[nt][0]); p01 = __expf(s4[nt][1]); }
            else   { p00 = 1.f; p01 = 1.f; }
            if(m1v){ p10 = __expf(s4[nt][2]); p11 = __expf(s4[nt][3]); }
            else   { p10 = 1.f; p11 = 1.f; }
            lsum0 += p00 + p01;
            lsum1 += p10 + p11;
            pr0[cc] = tf32r(p00); pr0[cc+1] = tf32r(p01);
            pr1[cc] = tf32r(p10); pr1[cc+1] = tf32r(p11);
        }
        __syncthreads();

        // O += P @ V  (k = 128 keys -> 16 k-steps, n = 64 dims -> 8 n-tiles)
#pragma unroll
        for(int k8=0;k8<16;k8++){
            uint32_t ap[4];
            const float* pp  = &Ps[(w*16 + g)*132 + k8*8];
            const float* pp8 = pp + 8*132;
            ap[0] = __float_as_uint(pp[tig]);
            ap[1] = __float_as_uint(pp8[tig]);
            ap[2] = __float_as_uint(pp[tig+4]);
            ap[3] = __float_as_uint(pp8[tig+4]);
#pragma unroll
            for(int nt=0;nt<8;nt++){
                const float* vr = &Vs[(nt*8 + g)*132 + k8*8];
                uint32_t bb[2] = { __float_as_uint(vr[tig]), __float_as_uint(vr[tig+4]) };
                mma8(o[nt], ap, bb);
            }
        }
        __syncthreads();
    }

    // reduce row sums across the 4 lanes of the quad (same rows, different cols)
    lsum0 += __shfl_xor_sync(0xffffffffu, lsum0, 1);
    lsum0 += __shfl_xor_sync(0xffffffffu, lsum0, 2);
    lsum1 += __shfl_xor_sync(0xffffffffu, lsum1, 1);
    lsum1 += __shfl_xor_sync(0xffffffffu, lsum1, 2);
    const float inv0 = 1.f / lsum0;
    const float inv1 = 1.f / lsum1;

    // write O (tf32-rounded: it feeds the output projection)
    const size_t r0 = (size_t)(b*SEQ + row0g)*HID + h*DH;
    const size_t r1 = r0 + 8*HID;
#pragma unroll
    for(int nt=0;nt<8;nt++){
        const int cc = nt*8 + 2*tig;
        *(float2*)&Hb[r0 + cc] = make_float2(tf32r(o[nt][0]*inv0), tf32r(o[nt][1]*inv0));
        *(float2*)&Hb[r1 + cc] = make_float2(tf32r(o[nt][2]*inv1), tf32r(o[nt][3]*inv1));
    }
}

// ---------------------------------------------------------------------------

extern "C" void kernel_launch(void* const* d_in, const int* in_sizes, int n_in,
                              void* d_out, int out_size)
{
    const float* q    = (const float*)d_in[0];
    const float* k    = (const float*)d_in[1];
    const float* v    = (const float*)d_in[2];
    const int*   mask = (const int*)  d_in[3];
    const float* wq   = (const float*)d_in[4];
    const float* bq   = (const float*)d_in[5];
    const float* wk   = (const float*)d_in[6];
    const float* bk   = (const float*)d_in[7];
    const float* wv   = (const float*)d_in[8];
    const float* bv   = (const float*)d_in[9];
    const float* wo   = (const float*)d_in[10];
    const float* bo   = (const float*)d_in[11];
    float* out = (float*)d_out;

    float *qr,*kr,*vr,*wqr,*wkr,*wvr,*wor,*Qp,*Kp,*Vt,*Hb;
    cudaGetSymbolAddress((void**)&qr,  g_qr);
    cudaGetSymbolAddress((void**)&kr,  g_kr);
    cudaGetSymbolAddress((void**)&vr,  g_vr);
    cudaGetSymbolAddress((void**)&wqr, g_wqr);
    cudaGetSymbolAddress((void**)&wkr, g_wkr);
    cudaGetSymbolAddress((void**)&wvr, g_wvr);
    cudaGetSymbolAddress((void**)&wor, g_wor);
    cudaGetSymbolAddress((void**)&Qp,  g_Qp);
    cudaGetSymbolAddress((void**)&Kp,  g_Kp);
    cudaGetSymbolAddress((void**)&Vt,  g_Vt);
    cudaGetSymbolAddress((void**)&Hb,  g_Hb);

    cudaFuncSetAttribute(gemm_ws, cudaFuncAttributeMaxDynamicSharedMemorySize, GW_SMEM);
    cudaFuncSetAttribute(attn_ws, cudaFuncAttributeMaxDynamicSharedMemorySize, AW_SMEM);

    // 0. round inputs + weights to tf32 (RNE)
    {
        const int n4 = MTOT*HID/4;
        round_k<<<n4/256, 256>>>(q, qr, n4);
        round_k<<<n4/256, 256>>>(k, kr, n4);
        round_k<<<n4/256, 256>>>(v, vr, n4);
        const int w4 = HID*HID/4;
        round_k<<<w4/256, 256>>>(wq, wqr, w4);
        round_k<<<w4/256, 256>>>(wk, wkr, w4);
        round_k<<<w4/256, 256>>>(wv, wvr, w4);
        round_k<<<w4/256, 256>>>(wo, wor, w4);
    }

    // 1. fused QKV projections (z: 0=Q scaled, 1=K, 2=V transposed per-head)
    dim3 gQKV(HID/128, MTOT/128, 3);
    gemm_ws<<<gQKV, 256, GW_SMEM>>>(qr, kr, vr, wqr, wkr, wvr, bq, bk, bv,
                                    Qp, Kp, Vt, -1);

    // 2. attention
    dim3 gF(SEQ/128, BATCH*NHEADS);
    attn_ws<<<gF, 256, AW_SMEM>>>(Qp, Kp, Vt, mask, Hb);

    // 3. output projection (plain fp32 out)
    dim3 gO(HID/128, MTOT/128, 1);
    gemm_ws<<<gO, 256, GW_SMEM>>>(Hb, Hb, Hb, wor, wor, wor, bo, bo, bo,
                                  out, out, out, 3);
}

// round 5
// speedup vs baseline: 4.0353x; 1.5822x over previous
#include <cuda_runtime.h>
#include <cuda_fp16.h>
#include <cstdint>

#define HID 1024
#define SEQ 2048
#define BATCH 4
#define NHEADS 16
#define DH 64
#define MTOT (BATCH*SEQ)

// ---------------- scratch (static device arrays are allowed) ---------------
__device__ __half g_qh[MTOT*HID];
__device__ __half g_kh[MTOT*HID];
__device__ __half g_vh[MTOT*HID];
__device__ __half g_wqh[HID*HID];
__device__ __half g_wkh[HID*HID];
__device__ __half g_wvh[HID*HID];
__device__ __half g_woh[HID*HID];
__device__ __half g_Qp[MTOT*HID];
__device__ __half g_Kp[MTOT*HID];
__device__ __half g_Vt[BATCH*NHEADS*DH*SEQ];   // [b,h,d,s]
__device__ __half g_Hb[MTOT*HID];

// ---------------- helpers ---------------------------------------------------
__device__ __forceinline__ uint32_t smem_u32(const void* p){
    uint32_t a;
    asm("{ .reg .u64 t; cvta.to.shared.u64 t, %1; cvt.u32.u64 %0, t; }":"=r"(a):"l"(p));
    return a;
}
__device__ __forceinline__ void cp16(const void* dst, const void* src){
    asm volatile("cp.async.cg.shared.global [%0], [%1], 16;"
                 ::"r"(smem_u32(dst)),"l"(src));
}
#define CP_COMMIT() asm volatile("cp.async.commit_group;":::"memory")
#define CP_WAIT1()  asm volatile("cp.async.wait_group 1;":::"memory")
#define CP_WAIT0()  asm volatile("cp.async.wait_group 0;":::"memory")

// mma.sync m16n8k16 fp16 (sm_75+, legal on plain sm_103 target)
__device__ __forceinline__ void mma16(float* d, const uint32_t* a, const uint32_t* b){
    asm volatile(
        "mma.sync.aligned.m16n8k16.row.col.f32.f16.f16.f32 "
        "{%0,%1,%2,%3}, {%4,%5,%6,%7}, {%8,%9}, {%0,%1,%2,%3};"
        : "+f"(d[0]),"+f"(d[1]),"+f"(d[2]),"+f"(d[3])
        : "r"(a[0]),"r"(a[1]),"r"(a[2]),"r"(a[3]),
          "r"(b[0]),"r"(b[1]));
}

// ---------------- fp32 -> fp16 (RNE) ----------------------------------------
__global__ void tohalf_k(const float* __restrict__ s, __half* __restrict__ d, int n4){
    int i = blockIdx.x*256 + threadIdx.x;
    if(i < n4){
        float4 v = ((const float4*)s)[i];
        __half2* o = (__half2*)d + 2*i;
        o[0] = __floats2half2_rn(v.x, v.y);
        o[1] = __floats2half2_rn(v.z, v.w);
    }
}

// ---------------- warp-MMA GEMM: C = A @ W^T + bias (fp16 in, fp32 acc) -----
// Block 128x128, 8 warps (4x2), warp tile 32x64. K chunks of 64, double buffer.
// modes: 0=Q(bias,*0.125,half) 1=K(half) 2=V(half, per-head transpose) 3=float
#define GH_SMEM (4*128*72*2)
__global__ __launch_bounds__(256,1) void gemm_hs(
    const __half* __restrict__ A0, const __half* __restrict__ A1, const __half* __restrict__ A2,
    const __half* __restrict__ W0, const __half* __restrict__ W1, const __half* __restrict__ W2,
    const float* __restrict__ b0, const float* __restrict__ b1, const float* __restrict__ b2,
    void* __restrict__ C0, void* __restrict__ C1, void* __restrict__ C2,
    int mode_in)
{
    extern __shared__ __half smh[];
    const int z = blockIdx.z;
    const __half* A    = (z==0)?A0:(z==1)?A1:A2;
    const __half* W    = (z==0)?W0:(z==1)?W1:W2;
    const float*  bias = (z==0)?b0:(z==1)?b1:b2;
    void*         C    = (z==0)?C0:(z==1)?C1:C2;
    const int mode = (mode_in < 0) ? z : mode_in;

    __half* As[2] = { smh,            smh + 128*72 };
    __half* Ws[2] = { smh + 2*128*72, smh + 3*128*72 };

    const int t    = threadIdx.x;
    const int w    = t >> 5;
    const int lane = t & 31;
    const int g    = lane >> 2;
    const int tig  = lane & 3;
    const int wm   = (w >> 1) * 32;
    const int wn   = (w & 1) * 64;
    const int m0   = blockIdx.y * 128;
    const int n0   = blockIdx.x * 128;

    float acc[2][8][4];
#pragma unroll
    for(int mt=0;mt<2;mt++)
#pragma unroll
        for(int nt=0;nt<8;nt++)
#pragma unroll
            for(int i2=0;i2<4;i2++) acc[mt][nt][i2]=0.f;

    // prologue: chunk 0 (K=64 halves per row = 8 cp16 per row)
#pragma unroll
    for(int i=0;i<4;i++){
        int s = t + 256*i; int r = s>>3, c8 = s&7;
        cp16(&As[0][r*72 + c8*8], A + (size_t)(m0+r)*HID + c8*8);
        cp16(&Ws[0][r*72 + c8*8], W + (size_t)(n0+r)*HID + c8*8);
    }
    CP_COMMIT();

    for(int c=0;c<16;c++){
        const int buf = c & 1;
        if(c+1 < 16){
            const int k0 = (c+1)*64, nb = (c+1)&1;
#pragma unroll
            for(int i=0;i<4;i++){
                int s = t + 256*i; int r = s>>3, c8 = s&7;
                cp16(&As[nb][r*72 + c8*8], A + (size_t)(m0+r)*HID + k0 + c8*8);
                cp16(&Ws[nb][r*72 + c8*8], W + (size_t)(n0+r)*HID + k0 + c8*8);
            }
            CP_COMMIT();
            CP_WAIT1();
        } else {
            CP_WAIT0();
        }
        __syncthreads();

#pragma unroll
        for(int k16=0;k16<4;k16++){
            const int kk = k16*16;
            uint32_t a[2][4], b[8][2];
#pragma unroll
            for(int mt=0;mt<2;mt++){
                const __half* ar = &As[buf][(wm + mt*16 + g)*72 + kk];
                a[mt][0] = *(const uint32_t*)&ar[2*tig];
                a[mt][1] = *(const uint32_t*)&ar[8*72 + 2*tig];
                a[mt][2] = *(const uint32_t*)&ar[2*tig + 8];
                a[mt][3] = *(const uint32_t*)&ar[8*72 + 2*tig + 8];
            }
#pragma unroll
            for(int nt=0;nt<8;nt++){
                const __half* br = &Ws[buf][(wn + nt*8 + g)*72 + kk];
                b[nt][0] = *(const uint32_t*)&br[2*tig];
                b[nt][1] = *(const uint32_t*)&br[2*tig + 8];
            }
#pragma unroll
            for(int mt=0;mt<2;mt++)
#pragma unroll
                for(int nt=0;nt<8;nt++)
                    mma16(acc[mt][nt], a[mt], b[nt]);
        }
        __syncthreads();
    }

    // epilogue
#pragma unroll
    for(int mt=0;mt<2;mt++){
        const int row0 = m0 + wm + mt*16 + g;
        const int row1 = row0 + 8;
#pragma unroll
        for(int nt=0;nt<8;nt++){
            const int col0 = n0 + wn + nt*8 + 2*tig;
            const float bb0 = bias[col0], bb1 = bias[col0+1];
            float v00 = acc[mt][nt][0] + bb0, v01 = acc[mt][nt][1] + bb1;
            float v10 = acc[mt][nt][2] + bb0, v11 = acc[mt][nt][3] + bb1;
            if(mode==0){ v00*=0.125f; v01*=0.125f; v10*=0.125f; v11*=0.125f; }
            if(mode==2){
                __half* Ch = (__half*)C;
                const int bb = row0 >> 11;
                const int s0 = row0 & 2047, s1 = row1 & 2047;
                const int h0 = col0 >> 6,  d0 = col0 & 63;
                const int h1 = (col0+1) >> 6, d1 = (col0+1) & 63;
                Ch[((size_t)(bb*NHEADS+h0)*DH + d0)*SEQ + s0] = __float2half_rn(v00);
                Ch[((size_t)(bb*NHEADS+h1)*DH + d1)*SEQ + s0] = __float2half_rn(v01);
                Ch[((size_t)(bb*NHEADS+h0)*DH + d0)*SEQ + s1] = __float2half_rn(v10);
                Ch[((size_t)(bb*NHEADS+h1)*DH + d1)*SEQ + s1] = __float2half_rn(v11);
            } else if(mode==3){
                float* Cf = (float*)C;
                *(float2*)&Cf[(size_t)row0*HID + col0] = make_float2(v00, v01);
                *(float2*)&Cf[(size_t)row1*HID + col0] = make_float2(v10, v11);
            } else {
                __half* Ch = (__half*)C;
                *(__half2*)&Ch[(size_t)row0*HID + col0] = __floats2half2_rn(v00, v01);
                *(__half2*)&Ch[(size_t)row1*HID + col0] = __floats2half2_rn(v10, v11);
            }
        }
    }
}

// ---------------- warp-MMA attention (fp16) ---------------------------------
// CTA = one (b,h) x 128 queries; 8 warps x 16 rows. 128-key tiles, K/V dbl-buf.
// halves: Qs 128*72 | Ks0/1 128*72 | Vs0/1 64*136 | Ps 128*136
#define AH_SMEM ((128*72 + 2*128*72 + 2*64*136 + 128*136)*2)
__global__ __launch_bounds__(256,1) void attn_hs(
    const __half* __restrict__ Qp, const __half* __restrict__ Kp,
    const __half* __restrict__ Vt, const int* __restrict__ mask,
    __half* __restrict__ Hb)
{
    extern __shared__ __half smh[];
    __half* Qs    = smh;                       // [128][72]
    __half* Ks[2] = { smh + 128*72, smh + 2*128*72 };
    __half* Vs[2] = { smh + 3*128*72, smh + 3*128*72 + 64*136 };
    __half* Ps    = smh + 3*128*72 + 2*64*136; // [128][136]

    const int t    = threadIdx.x;
    const int w    = t >> 5;
    const int lane = t & 31;
    const int g    = lane >> 2;
    const int tig  = lane & 3;
    const int bh = blockIdx.y;
    const int b  = bh >> 4, h = bh & 15;
    const int q0 = blockIdx.x * 128;

    // load Q tile + K/V tile 0 in one group
#pragma unroll
    for(int i=0;i<4;i++){
        int s = t + 256*i; int r = s>>3, c8 = s&7;
        cp16(&Qs[r*72 + c8*8], Qp + (size_t)(b*SEQ + q0 + r)*HID + h*DH + c8*8);
        cp16(&Ks[0][r*72 + c8*8], Kp + (size_t)(b*SEQ + r)*HID + h*DH + c8*8);
    }
#pragma unroll
    for(int i=0;i<4;i++){
        int s = t + 256*i; int d = s>>4, c8 = s&15;
        cp16(&Vs[0][d*136 + c8*8], Vt + ((size_t)(b*NHEADS+h)*DH + d)*SEQ + c8*8);
    }
    CP_COMMIT();

    const int row0g = q0 + w*16 + g;
    const int m0v = mask[b*SEQ + row0g];
    const int m1v = mask[b*SEQ + row0g + 8];

    float o[8][4];
#pragma unroll
    for(int nt=0;nt<8;nt++)
#pragma unroll
        for(int i2=0;i2<4;i2++) o[nt][i2]=0.f;
    float lsum0 = 0.f, lsum1 = 0.f;

    uint32_t aq[4][4];
    bool have_q = false;

    for(int kt=0; kt<16; kt++){
        const int buf = kt & 1;
        if(kt+1 < 16){
            const int nb = buf ^ 1;
            const size_t krow = (size_t)(b*SEQ + (kt+1)*128);
#pragma unroll
            for(int i=0;i<4;i++){
                int s = t + 256*i; int r = s>>3, c8 = s&7;
                cp16(&Ks[nb][r*72 + c8*8], Kp + (krow + r)*HID + h*DH + c8*8);
            }
#pragma unroll
            for(int i=0;i<4;i++){
                int s = t + 256*i; int d = s>>4, c8 = s&15;
                cp16(&Vs[nb][d*136 + c8*8],
                     Vt + ((size_t)(b*NHEADS+h)*DH + d)*SEQ + (kt+1)*128 + c8*8);
            }
            CP_COMMIT();
            CP_WAIT1();
        } else {
            CP_WAIT0();
        }
        __syncthreads();

        if(!have_q){
            have_q = true;
#pragma unroll
            for(int k16=0;k16<4;k16++){
                const __half* qr = &Qs[(w*16 + g)*72 + k16*16];
                aq[k16][0] = *(const uint32_t*)&qr[2*tig];
                aq[k16][1] = *(const uint32_t*)&qr[8*72 + 2*tig];
                aq[k16][2] = *(const uint32_t*)&qr[2*tig + 8];
                aq[k16][3] = *(const uint32_t*)&qr[8*72 + 2*tig + 8];
            }
        }

        // S = Q @ K^T (Q carries 1/8); warp computes 16x128
        float s4[16][4];
#pragma unroll
        for(int nt=0;nt<16;nt++)
#pragma unroll
            for(int i2=0;i2<4;i2++) s4[nt][i2]=0.f;
#pragma unroll
        for(int k16=0;k16<4;k16++){
#pragma unroll
            for(int nt=0;nt<16;nt++){
                const __half* br = &Ks[buf][(nt*8 + g)*72 + k16*16];
                uint32_t bb[2] = { *(const uint32_t*)&br[2*tig],
                                   *(const uint32_t*)&br[2*tig + 8] };
                mma16(s4[nt], aq[k16], bb);
            }
        }

        // P = exp(S) (masked rows -> 1), accumulate row sums, stage to smem fp16
        __half* pr0 = &Ps[(w*16 + g)*136];
        __half* pr1 = pr0 + 8*136;
#pragma unroll
        for(int nt=0;nt<16;nt++){
            const int cc = nt*8 + 2*tig;
            float p00, p01, p10, p11;
            if(m0v){ p00 = __expf(s4[nt][0]); p01 = __expf(s4[nt][1]); }
            else   { p00 = 1.f; p01 = 1.f; }
            if(m1v){ p10 = __expf(s4[nt][2]); p11 = __expf(s4[nt][3]); }
            else   { p10 = 1.f; p11 = 1.f; }
            lsum0 += p00 + p01;
            lsum1 += p10 + p11;
            *(__half2*)&pr0[cc] = __floats2half2_rn(p00, p01);
            *(__half2*)&pr1[cc] = __floats2half2_rn(p10, p11);
        }
        __syncthreads();

        // O += P @ V  (k = 128 keys -> 8 k16-steps, n = 64 dims -> 8 n-tiles)
#pragma unroll
        for(int k16=0;k16<8;k16++){
            uint32_t ap[4];
            const __half* pp = &Ps[(w*16 + g)*136 + k16*16];
            ap[0] = *(const uint32_t*)&pp[2*tig];
            ap[1] = *(const uint32_t*)&pp[8*136 + 2*tig];
            ap[2] = *(const uint32_t*)&pp[2*tig + 8];
            ap[3] = *(const uint32_t*)&pp[8*136 + 2*tig + 8];
#pragma unroll
            for(int nt=0;nt<8;nt++){
                const __half* vr = &Vs[buf][(nt*8 + g)*136 + k16*16];
                uint32_t bb[2] = { *(const uint32_t*)&vr[2*tig],
                                   *(const uint32_t*)&vr[2*tig + 8] };
                mma16(o[nt], ap, bb);
            }
        }
        __syncthreads();
    }

    // reduce row sums across the lane quad
    lsum0 += __shfl_xor_sync(0xffffffffu, lsum0, 1);
    lsum0 += __shfl_xor_sync(0xffffffffu, lsum0, 2);
    lsum1 += __shfl_xor_sync(0xffffffffu, lsum1, 1);
    lsum1 += __shfl_xor_sync(0xffffffffu, lsum1, 2);
    const float inv0 = 1.f / lsum0;
    const float inv1 = 1.f / lsum1;

    // write O (fp16: feeds the output projection)
    const size_t r0 = (size_t)(b*SEQ + row0g)*HID + h*DH;
    const size_t r1 = r0 + 8*HID;
#pragma unroll
    for(int nt=0;nt<8;nt++){
        const int cc = nt*8 + 2*tig;
        *(__half2*)&Hb[r0 + cc] = __floats2half2_rn(o[nt][0]*inv0, o[nt][1]*inv0);
        *(__half2*)&Hb[r1 + cc] = __floats2half2_rn(o[nt][2]*inv1, o[nt][3]*inv1);
    }
}

// ---------------------------------------------------------------------------

extern "C" void kernel_launch(void* const* d_in, const int* in_sizes, int n_in,
                              void* d_out, int out_size)
{
    const float* q    = (const float*)d_in[0];
    const float* k    = (const float*)d_in[1];
    const float* v    = (const float*)d_in[2];
    const int*   mask = (const int*)  d_in[3];
    const float* wq   = (const float*)d_in[4];
    const float* bq   = (const float*)d_in[5];
    const float* wk   = (const float*)d_in[6];
    const float* bk   = (const float*)d_in[7];
    const float* wv   = (const float*)d_in[8];
    const float* bv   = (const float*)d_in[9];
    const float* wo   = (const float*)d_in[10];
    const float* bo   = (const float*)d_in[11];
    float* out = (float*)d_out;

    __half *qh,*kh,*vh,*wqh,*wkh,*wvh,*woh,*Qp,*Kp,*Vt,*Hb;
    cudaGetSymbolAddress((void**)&qh,  g_qh);
    cudaGetSymbolAddress((void**)&kh,  g_kh);
    cudaGetSymbolAddress((void**)&vh,  g_vh);
    cudaGetSymbolAddress((void**)&wqh, g_wqh);
    cudaGetSymbolAddress((void**)&wkh, g_wkh);
    cudaGetSymbolAddress((void**)&wvh, g_wvh);
    cudaGetSymbolAddress((void**)&woh, g_woh);
    cudaGetSymbolAddress((void**)&Qp,  g_Qp);
    cudaGetSymbolAddress((void**)&Kp,  g_Kp);
    cudaGetSymbolAddress((void**)&Vt,  g_Vt);
    cudaGetSymbolAddress((void**)&Hb,  g_Hb);

    cudaFuncSetAttribute(gemm_hs, cudaFuncAttributeMaxDynamicSharedMemorySize, GH_SMEM);
    cudaFuncSetAttribute(attn_hs, cudaFuncAttributeMaxDynamicSharedMemorySize, AH_SMEM);

    // 0. convert inputs + weights to fp16 (RNE)
    {
        const int n4 = MTOT*HID/4;
        tohalf_k<<<n4/256, 256>>>(q, qh, n4);
        tohalf_k<<<n4/256, 256>>>(k, kh, n4);
        tohalf_k<<<n4/256, 256>>>(v, vh, n4);
        const int w4 = HID*HID/4;
        tohalf_k<<<w4/256, 256>>>(wq, wqh, w4);
        tohalf_k<<<w4/256, 256>>>(wk, wkh, w4);
        tohalf_k<<<w4/256, 256>>>(wv, wvh, w4);
        tohalf_k<<<w4/256, 256>>>(wo, woh, w4);
    }

    // 1. fused QKV projections (z: 0=Q scaled, 1=K, 2=V transposed per-head)
    dim3 gQKV(HID/128, MTOT/128, 3);
    gemm_hs<<<gQKV, 256, GH_SMEM>>>(qh, kh, vh, wqh, wkh, wvh, bq, bk, bv,
                                    Qp, Kp, Vt, -1);

    // 2. attention
    dim3 gF(SEQ/128, BATCH*NHEADS);
    attn_hs<<<gF, 256, AH_SMEM>>>(Qp, Kp, Vt, mask, Hb);

    // 3. output projection (fp32 out)
    dim3 gO(HID/128, MTOT/128, 1);
    gemm_hs<<<gO, 256, GH_SMEM>>>(Hb, Hb, Hb, woh, woh, woh, bo, bo, bo,
                                  out, out, out, 3);
}

// round 6
// speedup vs baseline: 4.8056x; 1.1909x over previous
#include <cuda_runtime.h>
#include <cuda_fp16.h>
#include <cstdint>

#define HID 1024
#define SEQ 2048
#define BATCH 4
#define NHEADS 16
#define DH 64
#define MTOT (BATCH*SEQ)

// ---------------- scratch (static device arrays are allowed) ---------------
__device__ __half g_qh[MTOT*HID];
__device__ __half g_kh[MTOT*HID];
__device__ __half g_vh[MTOT*HID];
__device__ __half g_wqh[HID*HID];
__device__ __half g_wkh[HID*HID];
__device__ __half g_wvh[HID*HID];
__device__ __half g_woh[HID*HID];
__device__ __half g_Qp[MTOT*HID];
__device__ __half g_Kp[MTOT*HID];
__device__ __half g_Vt[BATCH*NHEADS*DH*SEQ];   // [b,h,d,s]
__device__ __half g_Hb[MTOT*HID];

// ---------------- helpers ---------------------------------------------------
__device__ __forceinline__ uint32_t smem_u32(const void* p){
    uint32_t a;
    asm("{ .reg .u64 t; cvta.to.shared.u64 t, %1; cvt.u32.u64 %0, t; }":"=r"(a):"l"(p));
    return a;
}
__device__ __forceinline__ void cp16(const void* dst, const void* src){
    asm volatile("cp.async.cg.shared.global [%0], [%1], 16;"
                 ::"r"(smem_u32(dst)),"l"(src));
}
#define CP_COMMIT() asm volatile("cp.async.commit_group;":::"memory")
#define CP_WAIT1()  asm volatile("cp.async.wait_group 1;":::"memory")
#define CP_WAIT0()  asm volatile("cp.async.wait_group 0;":::"memory")

// mma.sync m16n8k16 fp16 (sm_75+, legal on plain sm_103 target)
__device__ __forceinline__ void mma16(float* d, const uint32_t* a,
                                      uint32_t b0, uint32_t b1){
    asm volatile(
        "mma.sync.aligned.m16n8k16.row.col.f32.f16.f16.f32 "
        "{%0,%1,%2,%3}, {%4,%5,%6,%7}, {%8,%9}, {%0,%1,%2,%3};"
        : "+f"(d[0]),"+f"(d[1]),"+f"(d[2]),"+f"(d[3])
        : "r"(a[0]),"r"(a[1]),"r"(a[2]),"r"(a[3]),
          "r"(b0),"r"(b1));
}
// ldmatrix x4 (sm_75+)
__device__ __forceinline__ void ldm4(uint32_t* r, const void* p){
    asm volatile("ldmatrix.sync.aligned.m8n8.x4.shared.b16 {%0,%1,%2,%3}, [%4];"
        : "=r"(r[0]),"=r"(r[1]),"=r"(r[2]),"=r"(r[3]) : "r"(smem_u32(p)));
}

// ---------------- fused fp32 -> fp16 conversions (one launch) ---------------
__global__ void tohalf_all(
    const float* __restrict__ q, const float* __restrict__ k, const float* __restrict__ v,
    const float* __restrict__ wq, const float* __restrict__ wk,
    const float* __restrict__ wv, const float* __restrict__ wo,
    __half* __restrict__ qh, __half* __restrict__ kh, __half* __restrict__ vh,
    __half* __restrict__ wqh, __half* __restrict__ wkh,
    __half* __restrict__ wvh, __half* __restrict__ woh)
{
    const int which = blockIdx.y;
    const float* s; __half* d; int n4;
    switch(which){
        case 0: s=q;  d=qh;  n4=MTOT*HID/4; break;
        case 1: s=k;  d=kh;  n4=MTOT*HID/4; break;
        case 2: s=v;  d=vh;  n4=MTOT*HID/4; break;
        case 3: s=wq; d=wqh; n4=HID*HID/4;  break;
        case 4: s=wk; d=wkh; n4=HID*HID/4;  break;
        case 5: s=wv; d=wvh; n4=HID*HID/4;  break;
        default:s=wo; d=woh; n4=HID*HID/4;  break;
    }
    int i = blockIdx.x*256 + threadIdx.x;
    if(i < n4){
        float4 vv = ((const float4*)s)[i];
        __half2* o = (__half2*)d + 2*i;
        o[0] = __floats2half2_rn(vv.x, vv.y);
        o[1] = __floats2half2_rn(vv.z, vv.w);
    }
}

// ---------------- warp-MMA GEMM: C = A @ W^T + bias (fp16 in, fp32 acc) -----
// Block 128x128, 8 warps (4x2), warp tile 32x64. K chunks of 64, double buffer.
// modes: 0=Q(bias,*0.125,half) 1=K(half) 2=V(half, per-head transpose) 3=float
#define GH_SMEM (4*128*72*2)
__global__ __launch_bounds__(256,1) void gemm_hs(
    const __half* __restrict__ A0, const __half* __restrict__ A1, const __half* __restrict__ A2,
    const __half* __restrict__ W0, const __half* __restrict__ W1, const __half* __restrict__ W2,
    const float* __restrict__ b0, const float* __restrict__ b1, const float* __restrict__ b2,
    void* __restrict__ C0, void* __restrict__ C1, void* __restrict__ C2,
    int mode_in)
{
    extern __shared__ __half smh[];
    const int z = blockIdx.z;
    const __half* A    = (z==0)?A0:(z==1)?A1:A2;
    const __half* W    = (z==0)?W0:(z==1)?W1:W2;
    const float*  bias = (z==0)?b0:(z==1)?b1:b2;
    void*         C    = (z==0)?C0:(z==1)?C1:C2;
    const int mode = (mode_in < 0) ? z : mode_in;

    __half* As[2] = { smh,            smh + 128*72 };
    __half* Ws[2] = { smh + 2*128*72, smh + 3*128*72 };

    const int t    = threadIdx.x;
    const int w    = t >> 5;
    const int lane = t & 31;
    const int g    = lane >> 2;
    const int tig  = lane & 3;
    const int wm   = (w >> 1) * 32;
    const int wn   = (w & 1) * 64;
    const int m0   = blockIdx.y * 128;
    const int n0   = blockIdx.x * 128;

    // ldmatrix lane->address components
    const int aRow = wm + (lane & 15);
    const int aCol = (lane >> 4) * 8;
    const int bRow = wn + ((lane >> 4) & 1) * 8 + (lane & 7);
    const int bCol = ((lane >> 3) & 1) * 8;

    float acc[2][8][4];
#pragma unroll
    for(int mt=0;mt<2;mt++)
#pragma unroll
        for(int nt=0;nt<8;nt++)
#pragma unroll
            for(int i2=0;i2<4;i2++) acc[mt][nt][i2]=0.f;

    // prologue: chunk 0
#pragma unroll
    for(int i=0;i<4;i++){
        int s = t + 256*i; int r = s>>3, c8 = s&7;
        cp16(&As[0][r*72 + c8*8], A + (size_t)(m0+r)*HID + c8*8);
        cp16(&Ws[0][r*72 + c8*8], W + (size_t)(n0+r)*HID + c8*8);
    }
    CP_COMMIT();

    for(int c=0;c<16;c++){
        const int buf = c & 1;
        if(c+1 < 16){
            const int k0 = (c+1)*64, nb = (c+1)&1;
#pragma unroll
            for(int i=0;i<4;i++){
                int s = t + 256*i; int r = s>>3, c8 = s&7;
                cp16(&As[nb][r*72 + c8*8], A + (size_t)(m0+r)*HID + k0 + c8*8);
                cp16(&Ws[nb][r*72 + c8*8], W + (size_t)(n0+r)*HID + k0 + c8*8);
            }
            CP_COMMIT();
            CP_WAIT1();
        } else {
            CP_WAIT0();
        }
        __syncthreads();

        const __half* aBase = &As[buf][aRow*72 + aCol];
        const __half* bBase = &Ws[buf][bRow*72 + bCol];
#pragma unroll
        for(int k16=0;k16<4;k16++){
            const int kk = k16*16;
            uint32_t a[2][4];
            ldm4(a[0], aBase + kk);
            ldm4(a[1], aBase + 16*72 + kk);
#pragma unroll
            for(int p=0;p<4;p++){
                uint32_t bb[4];
                ldm4(bb, bBase + p*16*72 + kk);
#pragma unroll
                for(int mt=0;mt<2;mt++){
                    mma16(acc[mt][2*p],   a[mt], bb[0], bb[1]);
                    mma16(acc[mt][2*p+1], a[mt], bb[2], bb[3]);
                }
            }
        }
        __syncthreads();
    }

    // epilogue
#pragma unroll
    for(int mt=0;mt<2;mt++){
        const int row0 = m0 + wm + mt*16 + g;
        const int row1 = row0 + 8;
#pragma unroll
        for(int nt=0;nt<8;nt++){
            const int col0 = n0 + wn + nt*8 + 2*tig;
            const float bb0 = bias[col0], bb1 = bias[col0+1];
            float v00 = acc[mt][nt][0] + bb0, v01 = acc[mt][nt][1] + bb1;
            float v10 = acc[mt][nt][2] + bb0, v11 = acc[mt][nt][3] + bb1;
            if(mode==0){ v00*=0.125f; v01*=0.125f; v10*=0.125f; v11*=0.125f; }
            if(mode==2){
                __half* Ch = (__half*)C;
                const int bb = row0 >> 11;
                const int s0 = row0 & 2047, s1 = row1 & 2047;
                const int h0 = col0 >> 6,  d0 = col0 & 63;
                const int h1 = (col0+1) >> 6, d1 = (col0+1) & 63;
                Ch[((size_t)(bb*NHEADS+h0)*DH + d0)*SEQ + s0] = __float2half_rn(v00);
                Ch[((size_t)(bb*NHEADS+h1)*DH + d1)*SEQ + s0] = __float2half_rn(v01);
                Ch[((size_t)(bb*NHEADS+h0)*DH + d0)*SEQ + s1] = __float2half_rn(v10);
                Ch[((size_t)(bb*NHEADS+h1)*DH + d1)*SEQ + s1] = __float2half_rn(v11);
            } else if(mode==3){
                float* Cf = (float*)C;
                *(float2*)&Cf[(size_t)row0*HID + col0] = make_float2(v00, v01);
                *(float2*)&Cf[(size_t)row1*HID + col0] = make_float2(v10, v11);
            } else {
                __half* Ch = (__half*)C;
                *(__half2*)&Ch[(size_t)row0*HID + col0] = __floats2half2_rn(v00, v01);
                *(__half2*)&Ch[(size_t)row1*HID + col0] = __floats2half2_rn(v10, v11);
            }
        }
    }
}

// ---------------- warp-MMA attention (fp16, ldmatrix) -----------------------
// CTA = one (b,h) x 128 queries; 8 warps x 16 rows. 128-key tiles, K/V dbl-buf.
#define AH_SMEM ((128*72 + 2*128*72 + 2*64*136 + 128*136)*2)
__global__ __launch_bounds__(256,1) void attn_hs(
    const __half* __restrict__ Qp, const __half* __restrict__ Kp,
    const __half* __restrict__ Vt, const int* __restrict__ mask,
    __half* __restrict__ Hb)
{
    extern __shared__ __half smh[];
    __half* Qs    = smh;                       // [128][72]
    __half* Ks[2] = { smh + 128*72, smh + 2*128*72 };
    __half* Vs[2] = { smh + 3*128*72, smh + 3*128*72 + 64*136 };
    __half* Ps    = smh + 3*128*72 + 2*64*136; // [128][136]

    const int t    = threadIdx.x;
    const int w    = t >> 5;
    const int lane = t & 31;
    const int g    = lane >> 2;
    const int tig  = lane & 3;
    const int bh = blockIdx.y;
    const int b  = bh >> 4, h = bh & 15;
    const int q0 = blockIdx.x * 128;

    // ldmatrix lane->address components
    const int aRow = w*16 + (lane & 15);        // A-role rows (Q, P)
    const int aCol = (lane >> 4) * 8;
    const int bRow = ((lane >> 4) & 1) * 8 + (lane & 7);  // B-role rows (K, V)
    const int bCol = ((lane >> 3) & 1) * 8;

    // load Q tile + K/V tile 0 in one group
#pragma unroll
    for(int i=0;i<4;i++){
        int s = t + 256*i; int r = s>>3, c8 = s&7;
        cp16(&Qs[r*72 + c8*8], Qp + (size_t)(b*SEQ + q0 + r)*HID + h*DH + c8*8);
        cp16(&Ks[0][r*72 + c8*8], Kp + (size_t)(b*SEQ + r)*HID + h*DH + c8*8);
    }
#pragma unroll
    for(int i=0;i<4;i++){
        int s = t + 256*i; int d = s>>4, c8 = s&15;
        cp16(&Vs[0][d*136 + c8*8], Vt + ((size_t)(b*NHEADS+h)*DH + d)*SEQ + c8*8);
    }
    CP_COMMIT();

    const int row0g = q0 + w*16 + g;
    const int m0v = mask[b*SEQ + row0g];
    const int m1v = mask[b*SEQ + row0g + 8];

    float o[8][4];
#pragma unroll
    for(int nt=0;nt<8;nt++)
#pragma unroll
        for(int i2=0;i2<4;i2++) o[nt][i2]=0.f;
    float lsum0 = 0.f, lsum1 = 0.f;

    uint32_t aq[4][4];

    for(int kt=0; kt<16; kt++){
        const int buf = kt & 1;
        if(kt+1 < 16){
            const int nb = buf ^ 1;
            const size_t krow = (size_t)(b*SEQ + (kt+1)*128);
#pragma unroll
            for(int i=0;i<4;i++){
                int s = t + 256*i; int r = s>>3, c8 = s&7;
                cp16(&Ks[nb][r*72 + c8*8], Kp + (krow + r)*HID + h*DH + c8*8);
            }
#pragma unroll
            for(int i=0;i<4;i++){
                int s = t + 256*i; int d = s>>4, c8 = s&15;
                cp16(&Vs[nb][d*136 + c8*8],
                     Vt + ((size_t)(b*NHEADS+h)*DH + d)*SEQ + (kt+1)*128 + c8*8);
            }
            CP_COMMIT();
            CP_WAIT1();
        } else {
            CP_WAIT0();
        }
        __syncthreads();

        if(kt==0){
            const __half* qBase = &Qs[aRow*72 + aCol];
#pragma unroll
            for(int k16=0;k16<4;k16++) ldm4(aq[k16], qBase + k16*16);
        }

        // S = Q @ K^T (Q carries 1/8); warp computes 16x128
        float s4[16][4];
#pragma unroll
        for(int nt=0;nt<16;nt++)
#pragma unroll
            for(int i2=0;i2<4;i2++) s4[nt][i2]=0.f;
        const __half* kBase = &Ks[buf][bRow*72 + bCol];
#pragma unroll
        for(int k16=0;k16<4;k16++){
            const int kk = k16*16;
#pragma unroll
            for(int p=0;p<8;p++){
                uint32_t bb[4];
                ldm4(bb, kBase + p*16*72 + kk);
                mma16(s4[2*p],   aq[k16], bb[0], bb[1]);
                mma16(s4[2*p+1], aq[k16], bb[2], bb[3]);
            }
        }

        // P = exp(S) (masked rows -> 1), accumulate row sums, stage to smem fp16
        __half* pr0 = &Ps[(w*16 + g)*136];
        __half* pr1 = pr0 + 8*136;
#pragma unroll
        for(int nt=0;nt<16;nt++){
            const int cc = nt*8 + 2*tig;
            float p00, p01, p10, p11;
            if(m0v){ p00 = __expf(s4[nt][0]); p01 = __expf(s4[nt][1]); }
            else   { p00 = 1.f; p01 = 1.f; }
            if(m1v){ p10 = __expf(s4[nt][2]); p11 = __expf(s4[nt][3]); }
            else   { p10 = 1.f; p11 = 1.f; }
            lsum0 += p00 + p01;
            lsum1 += p10 + p11;
            *(__half2*)&pr0[cc] = __floats2half2_rn(p00, p01);
            *(__half2*)&pr1[cc] = __floats2half2_rn(p10, p11);
        }
        __syncthreads();

        // O += P @ V  (k = 128 keys -> 8 k16-steps, n = 64 dims -> 4 x4-tiles)
        const __half* pBase = &Ps[aRow*136 + aCol];
        const __half* vBase = &Vs[buf][bRow*136 + bCol];
#pragma unroll
        for(int k16=0;k16<8;k16++){
            const int kk = k16*16;
            uint32_t ap[4];
            ldm4(ap, pBase + kk);
#pragma unroll
            for(int p=0;p<4;p++){
                uint32_t bb[4];
                ldm4(bb, vBase + p*16*136 + kk);
                mma16(o[2*p],   ap, bb[0], bb[1]);
                mma16(o[2*p+1], ap, bb[2], bb[3]);
            }
        }
        __syncthreads();
    }

    // reduce row sums across the lane quad
    lsum0 += __shfl_xor_sync(0xffffffffu, lsum0, 1);
    lsum0 += __shfl_xor_sync(0xffffffffu, lsum0, 2);
    lsum1 += __shfl_xor_sync(0xffffffffu, lsum1, 1);
    lsum1 += __shfl_xor_sync(0xffffffffu, lsum1, 2);
    const float inv0 = 1.f / lsum0;
    const float inv1 = 1.f / lsum1;

    // write O (fp16: feeds the output projection)
    const size_t r0 = (size_t)(b*SEQ + row0g)*HID + h*DH;
    const size_t r1 = r0 + 8*HID;
#pragma unroll
    for(int nt=0;nt<8;nt++){
        const int cc = nt*8 + 2*tig;
        *(__half2*)&Hb[r0 + cc] = __floats2half2_rn(o[nt][0]*inv0, o[nt][1]*inv0);
        *(__half2*)&Hb[r1 + cc] = __floats2half2_rn(o[nt][2]*inv1, o[nt][3]*inv1);
    }
}

// ---------------------------------------------------------------------------

extern "C" void kernel_launch(void* const* d_in, const int* in_sizes, int n_in,
                              void* d_out, int out_size)
{
    const float* q    = (const float*)d_in[0];
    const float* k    = (const float*)d_in[1];
    const float* v    = (const float*)d_in[2];
    const int*   mask = (const int*)  d_in[3];
    const float* wq   = (const float*)d_in[4];
    const float* bq   = (const float*)d_in[5];
    const float* wk   = (const float*)d_in[6];
    const float* bk   = (const float*)d_in[7];
    const float* wv   = (const float*)d_in[8];
    const float* bv   = (const float*)d_in[9];
    const float* wo   = (const float*)d_in[10];
    const float* bo   = (const float*)d_in[11];
    float* out = (float*)d_out;

    __half *qh,*kh,*vh,*wqh,*wkh,*wvh,*woh,*Qp,*Kp,*Vt,*Hb;
    cudaGetSymbolAddress((void**)&qh,  g_qh);
    cudaGetSymbolAddress((void**)&kh,  g_kh);
    cudaGetSymbolAddress((void**)&vh,  g_vh);
    cudaGetSymbolAddress((void**)&wqh, g_wqh);
    cudaGetSymbolAddress((void**)&wkh, g_wkh);
    cudaGetSymbolAddress((void**)&wvh, g_wvh);
    cudaGetSymbolAddress((void**)&woh, g_woh);
    cudaGetSymbolAddress((void**)&Qp,  g_Qp);
    cudaGetSymbolAddress((void**)&Kp,  g_Kp);
    cudaGetSymbolAddress((void**)&Vt,  g_Vt);
    cudaGetSymbolAddress((void**)&Hb,  g_Hb);

    cudaFuncSetAttribute(gemm_hs, cudaFuncAttributeMaxDynamicSharedMemorySize, GH_SMEM);
    cudaFuncSetAttribute(attn_hs, cudaFuncAttributeMaxDynamicSharedMemorySize, AH_SMEM);

    // 0. convert inputs + weights to fp16 (single launch)
    {
        dim3 gC(MTOT*HID/4/256, 7);
        tohalf_all<<<gC, 256>>>(q, k, v, wq, wk, wv, wo,
                                qh, kh, vh, wqh, wkh, wvh, woh);
    }

    // 1. fused QKV projections (z: 0=Q scaled, 1=K, 2=V transposed per-head)
    dim3 gQKV(HID/128, MTOT/128, 3);
    gemm_hs<<<gQKV, 256, GH_SMEM>>>(qh, kh, vh, wqh, wkh, wvh, bq, bk, bv,
                                    Qp, Kp, Vt, -1);

    // 2. attention
    dim3 gF(SEQ/128, BATCH*NHEADS);
    attn_hs<<<gF, 256, AH_SMEM>>>(Qp, Kp, Vt, mask, Hb);

    // 3. output projection (fp32 out)
    dim3 gO(HID/128, MTOT/128, 1);
    gemm_hs<<<gO, 256, GH_SMEM>>>(Hb, Hb, Hb, woh, woh, woh, bo, bo, bo,
                                  out, out, out, 3);
}

// round 9
// speedup vs baseline: 6.1836x; 1.2867x over previous
#include <cuda_runtime.h>
#include <cuda_fp16.h>
#include <cstdint>

#define HID 1024
#define SEQ 2048
#define BATCH 4
#define NHEADS 16
#define DH 64
#define MTOT (BATCH*SEQ)

// ---------------- scratch (static device arrays are allowed) ---------------
__device__ __half g_qh[MTOT*HID];
__device__ __half g_kh[MTOT*HID];
__device__ __half g_vh[MTOT*HID];
__device__ __half g_wqh[HID*HID];
__device__ __half g_wkh[HID*HID];
__device__ __half g_wvh[HID*HID];
__device__ __half g_woh[HID*HID];
__device__ __half g_Qp[MTOT*HID];
__device__ __half g_Kp[MTOT*HID];
__device__ __half g_Vt[BATCH*NHEADS*DH*SEQ];   // [b,h,d,s]
__device__ __half g_Hb[MTOT*HID];

// ---------------- helpers ---------------------------------------------------
__device__ __forceinline__ uint32_t smem_u32(const void* p){
    uint32_t a;
    asm("{ .reg .u64 t; cvta.to.shared.u64 t, %1; cvt.u32.u64 %0, t; }":"=r"(a):"l"(p));
    return a;
}
__device__ __forceinline__ void cp16(const void* dst, const void* src){
    asm volatile("cp.async.cg.shared.global [%0], [%1], 16;"
                 ::"r"(smem_u32(dst)),"l"(src));
}
#define CP_COMMIT() asm volatile("cp.async.commit_group;":::"memory")
#define CP_WAIT1()  asm volatile("cp.async.wait_group 1;":::"memory")
#define CP_WAIT0()  asm volatile("cp.async.wait_group 0;":::"memory")

// mma.sync m16n8k16 fp16 (sm_75+, legal on plain sm_103 target)
__device__ __forceinline__ void mma16(float* d, const uint32_t* a,
                                      uint32_t b0, uint32_t b1){
    asm volatile(
        "mma.sync.aligned.m16n8k16.row.col.f32.f16.f16.f32 "
        "{%0,%1,%2,%3}, {%4,%5,%6,%7}, {%8,%9}, {%0,%1,%2,%3};"
        : "+f"(d[0]),"+f"(d[1]),"+f"(d[2]),"+f"(d[3])
        : "r"(a[0]),"r"(a[1]),"r"(a[2]),"r"(a[3]),
          "r"(b0),"r"(b1));
}
// ldmatrix x4 (sm_75+)
__device__ __forceinline__ void ldm4(uint32_t* r, const void* p){
    asm volatile("ldmatrix.sync.aligned.m8n8.x4.shared.b16 {%0,%1,%2,%3}, [%4];"
        : "=r"(r[0]),"=r"(r[1]),"=r"(r[2]),"=r"(r[3]) : "r"(smem_u32(p)));
}
__device__ __forceinline__ uint32_t packh2(float x, float y){
    __half2 h = __floats2half2_rn(x, y);
    return *(uint32_t*)&h;
}

// ---------------- fused fp32 -> fp16 conversions (one launch) ---------------
__global__ void tohalf_all(
    const float* __restrict__ q, const float* __restrict__ k, const float* __restrict__ v,
    const float* __restrict__ wq, const float* __restrict__ wk,
    const float* __restrict__ wv, const float* __restrict__ wo,
    __half* __restrict__ qh, __half* __restrict__ kh, __half* __restrict__ vh,
    __half* __restrict__ wqh, __half* __restrict__ wkh,
    __half* __restrict__ wvh, __half* __restrict__ woh)
{
    const int which = blockIdx.y;
    const float* s; __half* d; int n4;
    switch(which){
        case 0: s=q;  d=qh;  n4=MTOT*HID/4; break;
        case 1: s=k;  d=kh;  n4=MTOT*HID/4; break;
        case 2: s=v;  d=vh;  n4=MTOT*HID/4; break;
        case 3: s=wq; d=wqh; n4=HID*HID/4;  break;
        case 4: s=wk; d=wkh; n4=HID*HID/4;  break;
        case 5: s=wv; d=wvh; n4=HID*HID/4;  break;
        default:s=wo; d=woh; n4=HID*HID/4;  break;
    }
    int i = blockIdx.x*256 + threadIdx.x;
    if(i < n4){
        float4 vv = ((const float4*)s)[i];
        __half2* o = (__half2*)d + 2*i;
        o[0] = __floats2half2_rn(vv.x, vv.y);
        o[1] = __floats2half2_rn(vv.z, vv.w);
    }
}

// ---------------- warp-MMA GEMM: C = A @ W^T + bias (fp16 in, fp32 acc) -----
// Block 128x128, 8 warps (4x2), warp tile 32x64. K chunks of 64, double buffer.
// 2 CTAs/SM for latency hiding.
// modes: 0=Q(bias,*0.125,half) 1=K(half) 2=V(half, per-head transpose) 3=float
#define GH_SMEM (4*128*72*2)
__global__ __launch_bounds__(256,2) void gemm_hs(
    const __half* __restrict__ A0, const __half* __restrict__ A1, const __half* __restrict__ A2,
    const __half* __restrict__ W0, const __half* __restrict__ W1, const __half* __restrict__ W2,
    const float* __restrict__ b0, const float* __restrict__ b1, const float* __restrict__ b2,
    void* __restrict__ C0, void* __restrict__ C1, void* __restrict__ C2,
    int mode_in)
{
    extern __shared__ __half smh[];
    const int z = blockIdx.z;
    const __half* A    = (z==0)?A0:(z==1)?A1:A2;
    const __half* W    = (z==0)?W0:(z==1)?W1:W2;
    const float*  bias = (z==0)?b0:(z==1)?b1:b2;
    void*         C    = (z==0)?C0:(z==1)?C1:C2;
    const int mode = (mode_in < 0) ? z : mode_in;

    __half* As[2] = { smh,            smh + 128*72 };
    __half* Ws[2] = { smh + 2*128*72, smh + 3*128*72 };

    const int t    = threadIdx.x;
    const int w    = t >> 5;
    const int lane = t & 31;
    const int g    = lane >> 2;
    const int tig  = lane & 3;
    const int wm   = (w >> 1) * 32;
    const int wn   = (w & 1) * 64;
    const int m0   = blockIdx.y * 128;
    const int n0   = blockIdx.x * 128;

    // ldmatrix lane->address components
    const int aRow = wm + (lane & 15);
    const int aCol = (lane >> 4) * 8;
    const int bRow = wn + ((lane >> 4) & 1) * 8 + (lane & 7);
    const int bCol = ((lane >> 3) & 1) * 8;

    float acc[2][8][4];
#pragma unroll
    for(int mt=0;mt<2;mt++)
#pragma unroll
        for(int nt=0;nt<8;nt++)
#pragma unroll
            for(int i2=0;i2<4;i2++) acc[mt][nt][i2]=0.f;

    // prologue: chunk 0
#pragma unroll
    for(int i=0;i<4;i++){
        int s = t + 256*i; int r = s>>3, c8 = s&7;
        cp16(&As[0][r*72 + c8*8], A + (size_t)(m0+r)*HID + c8*8);
        cp16(&Ws[0][r*72 + c8*8], W + (size_t)(n0+r)*HID + c8*8);
    }
    CP_COMMIT();

    for(int c=0;c<16;c++){
        const int buf = c & 1;
        if(c+1 < 16){
            const int k0 = (c+1)*64, nb = (c+1)&1;
#pragma unroll
            for(int i=0;i<4;i++){
                int s = t + 256*i; int r = s>>3, c8 = s&7;
                cp16(&As[nb][r*72 + c8*8], A + (size_t)(m0+r)*HID + k0 + c8*8);
                cp16(&Ws[nb][r*72 + c8*8], W + (size_t)(n0+r)*HID + k0 + c8*8);
            }
            CP_COMMIT();
            CP_WAIT1();
        } else {
            CP_WAIT0();
        }
        __syncthreads();

        const __half* aBase = &As[buf][aRow*72 + aCol];
        const __half* bBase = &Ws[buf][bRow*72 + bCol];
#pragma unroll
        for(int k16=0;k16<4;k16++){
            const int kk = k16*16;
            uint32_t a[2][4];
            ldm4(a[0], aBase + kk);
            ldm4(a[1], aBase + 16*72 + kk);
#pragma unroll
            for(int p=0;p<4;p++){
                uint32_t bb[4];
                ldm4(bb, bBase + p*16*72 + kk);
#pragma unroll
                for(int mt=0;mt<2;mt++){
                    mma16(acc[mt][2*p],   a[mt], bb[0], bb[1]);
                    mma16(acc[mt][2*p+1], a[mt], bb[2], bb[3]);
                }
            }
        }
        __syncthreads();
    }

    // epilogue
#pragma unroll
    for(int mt=0;mt<2;mt++){
        const int row0 = m0 + wm + mt*16 + g;
        const int row1 = row0 + 8;
#pragma unroll
        for(int nt=0;nt<8;nt++){
            const int col0 = n0 + wn + nt*8 + 2*tig;
            const float bb0 = bias[col0], bb1 = bias[col0+1];
            float v00 = acc[mt][nt][0] + bb0, v01 = acc[mt][nt][1] + bb1;
            float v10 = acc[mt][nt][2] + bb0, v11 = acc[mt][nt][3] + bb1;
            if(mode==0){ v00*=0.125f; v01*=0.125f; v10*=0.125f; v11*=0.125f; }
            if(mode==2){
                __half* Ch = (__half*)C;
                const int bb = row0 >> 11;
                const int s0 = row0 & 2047, s1 = row1 & 2047;
                const int h0 = col0 >> 6,  d0 = col0 & 63;
                const int h1 = (col0+1) >> 6, d1 = (col0+1) & 63;
                Ch[((size_t)(bb*NHEADS+h0)*DH + d0)*SEQ + s0] = __float2half_rn(v00);
                Ch[((size_t)(bb*NHEADS+h1)*DH + d1)*SEQ + s0] = __float2half_rn(v01);
                Ch[((size_t)(bb*NHEADS+h0)*DH + d0)*SEQ + s1] = __float2half_rn(v10);
                Ch[((size_t)(bb*NHEADS+h1)*DH + d1)*SEQ + s1] = __float2half_rn(v11);
            } else if(mode==3){
                float* Cf = (float*)C;
                *(float2*)&Cf[(size_t)row0*HID + col0] = make_float2(v00, v01);
                *(float2*)&Cf[(size_t)row1*HID + col0] = make_float2(v10, v11);
            } else {
                __half* Ch = (__half*)C;
                *(__half2*)&Ch[(size_t)row0*HID + col0] = __floats2half2_rn(v00, v01);
                *(__half2*)&Ch[(size_t)row1*HID + col0] = __floats2half2_rn(v10, v11);
            }
        }
    }
}

// ---------------- warp-MMA attention (fp16, P in registers) -----------------
// CTA = one (b,h) x 128 queries; 8 warps x 16 rows. 128-key tiles, K/V dbl-buf.
// P never touches smem: S accum fragments repack directly into A fragments.
#define AH_SMEM ((128*72 + 2*128*72 + 2*64*136)*2)
__global__ __launch_bounds__(256,1) void attn_hs(
    const __half* __restrict__ Qp, const __half* __restrict__ Kp,
    const __half* __restrict__ Vt, const int* __restrict__ mask,
    __half* __restrict__ Hb)
{
    extern __shared__ __half smh[];
    __half* Qs    = smh;                       // [128][72]
    __half* Ks[2] = { smh + 128*72, smh + 2*128*72 };
    __half* Vs[2] = { smh + 3*128*72, smh + 3*128*72 + 64*136 };

    const int t    = threadIdx.x;
    const int w    = t >> 5;
    const int lane = t & 31;
    const int g    = lane >> 2;
    const int tig  = lane & 3;
    const int bh = blockIdx.y;
    const int b  = bh >> 4, h = bh & 15;
    const int q0 = blockIdx.x * 128;

    // ldmatrix lane->address components
    const int aRow = w*16 + (lane & 15);                  // A-role rows (Q)
    const int aCol = (lane >> 4) * 8;
    const int bRow = ((lane >> 4) & 1) * 8 + (lane & 7);  // B-role rows (K, V)
    const int bCol = ((lane >> 3) & 1) * 8;

    // load Q tile + K/V tile 0 in one group
#pragma unroll
    for(int i=0;i<4;i++){
        int s = t + 256*i; int r = s>>3, c8 = s&7;
        cp16(&Qs[r*72 + c8*8], Qp + (size_t)(b*SEQ + q0 + r)*HID + h*DH + c8*8);
        cp16(&Ks[0][r*72 + c8*8], Kp + (size_t)(b*SEQ + r)*HID + h*DH + c8*8);
    }
#pragma unroll
    for(int i=0;i<4;i++){
        int s = t + 256*i; int d = s>>4, c8 = s&15;
        cp16(&Vs[0][d*136 + c8*8], Vt + ((size_t)(b*NHEADS+h)*DH + d)*SEQ + c8*8);
    }
    CP_COMMIT();

    const int row0g = q0 + w*16 + g;
    const int m0v = mask[b*SEQ + row0g];
    const int m1v = mask[b*SEQ + row0g + 8];

    float o[8][4];
#pragma unroll
    for(int nt=0;nt<8;nt++)
#pragma unroll
        for(int i2=0;i2<4;i2++) o[nt][i2]=0.f;
    float lsum0 = 0.f, lsum1 = 0.f;

    uint32_t aq[4][4];

    for(int kt=0; kt<16; kt++){
        const int buf = kt & 1;
        if(kt+1 < 16){
            const int nb = buf ^ 1;
            const size_t krow = (size_t)(b*SEQ + (kt+1)*128);
#pragma unroll
            for(int i=0;i<4;i++){
                int s = t + 256*i; int r = s>>3, c8 = s&7;
                cp16(&Ks[nb][r*72 + c8*8], Kp + (krow + r)*HID + h*DH + c8*8);
            }
#pragma unroll
            for(int i=0;i<4;i++){
                int s = t + 256*i; int d = s>>4, c8 = s&15;
                cp16(&Vs[nb][d*136 + c8*8],
                     Vt + ((size_t)(b*NHEADS+h)*DH + d)*SEQ + (kt+1)*128 + c8*8);
            }
            CP_COMMIT();
            CP_WAIT1();
        } else {
            CP_WAIT0();
        }
        __syncthreads();

        if(kt==0){
            const __half* qBase = &Qs[aRow*72 + aCol];
#pragma unroll
            for(int k16=0;k16<4;k16++) ldm4(aq[k16], qBase + k16*16);
        }

        // S = Q @ K^T (Q carries 1/8); warp computes 16x128
        float s4[16][4];
#pragma unroll
        for(int nt=0;nt<16;nt++)
#pragma unroll
            for(int i2=0;i2<4;i2++) s4[nt][i2]=0.f;
        const __half* kBase = &Ks[buf][bRow*72 + bCol];
#pragma unroll
        for(int k16=0;k16<4;k16++){
            const int kk = k16*16;
#pragma unroll
            for(int p=0;p<8;p++){
                uint32_t bb[4];
                ldm4(bb, kBase + p*16*72 + kk);
                mma16(s4[2*p],   aq[k16], bb[0], bb[1]);
                mma16(s4[2*p+1], aq[k16], bb[2], bb[3]);
            }
        }

        // O += exp(S) @ V, with P fragments built directly from S accumulators.
        // For k16 step k, A-fragment = {pack(S[2k].c0,c1), pack(S[2k].c2,c3),
        //                               pack(S[2k+1].c0,c1), pack(S[2k+1].c2,c3)}
        const __half* vBase = &Vs[buf][bRow*136 + bCol];
#pragma unroll
        for(int k16=0;k16<8;k16++){
            float p00,p01,p02,p03, p10,p11,p12,p13;
            if(m0v){
                p00 = __expf(s4[2*k16][0]);   p01 = __expf(s4[2*k16][1]);
                p02 = __expf(s4[2*k16+1][0]); p03 = __expf(s4[2*k16+1][1]);
            } else { p00=p01=p02=p03=1.f; }
            if(m1v){
                p10 = __expf(s4[2*k16][2]);   p11 = __expf(s4[2*k16][3]);
                p12 = __expf(s4[2*k16+1][2]); p13 = __expf(s4[2*k16+1][3]);
            } else { p10=p11=p12=p13=1.f; }
            lsum0 += p00 + p01 + p02 + p03;
            lsum1 += p10 + p11 + p12 + p13;
            uint32_t ap[4];
            ap[0] = packh2(p00, p01);
            ap[1] = packh2(p10, p11);
            ap[2] = packh2(p02, p03);
            ap[3] = packh2(p12, p13);
            const int kk = k16*16;
#pragma unroll
            for(int p=0;p<4;p++){
                uint32_t bb[4];
                ldm4(bb, vBase + p*16*136 + kk);
                mma16(o[2*p],   ap, bb[0], bb[1]);
                mma16(o[2*p+1], ap, bb[2], bb[3]);
            }
        }
        __syncthreads();
    }

    // reduce row sums across the lane quad
    lsum0 += __shfl_xor_sync(0xffffffffu, lsum0, 1);
    lsum0 += __shfl_xor_sync(0xffffffffu, lsum0, 2);
    lsum1 += __shfl_xor_sync(0xffffffffu, lsum1, 1);
    lsum1 += __shfl_xor_sync(0xffffffffu, lsum1, 2);
    const float inv0 = 1.f / lsum0;
    const float inv1 = 1.f / lsum1;

    // write O (fp16: feeds the output projection)
    const size_t r0 = (size_t)(b*SEQ + row0g)*HID + h*DH;
    const size_t r1 = r0 + 8*HID;
#pragma unroll
    for(int nt=0;nt<8;nt++){
        const int cc = nt*8 + 2*tig;
        *(__half2*)&Hb[r0 + cc] = __floats2half2_rn(o[nt][0]*inv0, o[nt][1]*inv0);
        *(__half2*)&Hb[r1 + cc] = __floats2half2_rn(o[nt][2]*inv1, o[nt][3]*inv1);
    }
}

// ---------------------------------------------------------------------------

extern "C" void kernel_launch(void* const* d_in, const int* in_sizes, int n_in,
                              void* d_out, int out_size)
{
    const float* q    = (const float*)d_in[0];
    const float* k    = (const float*)d_in[1];
    const float* v    = (const float*)d_in[2];
    const int*   mask = (const int*)  d_in[3];
    const float* wq   = (const float*)d_in[4];
    const float* bq   = (const float*)d_in[5];
    const float* wk   = (const float*)d_in[6];
    const float* bk   = (const float*)d_in[7];
    const float* wv   = (const float*)d_in[8];
    const float* bv   = (const float*)d_in[9];
    const float* wo   = (const float*)d_in[10];
    const float* bo   = (const float*)d_in[11];
    float* out = (float*)d_out;

    __half *qh,*kh,*vh,*wqh,*wkh,*wvh,*woh,*Qp,*Kp,*Vt,*Hb;
    cudaGetSymbolAddress((void**)&qh,  g_qh);
    cudaGetSymbolAddress((void**)&kh,  g_kh);
    cudaGetSymbolAddress((void**)&vh,  g_vh);
    cudaGetSymbolAddress((void**)&wqh, g_wqh);
    cudaGetSymbolAddress((void**)&wkh, g_wkh);
    cudaGetSymbolAddress((void**)&wvh, g_wvh);
    cudaGetSymbolAddress((void**)&woh, g_woh);
    cudaGetSymbolAddress((void**)&Qp,  g_Qp);
    cudaGetSymbolAddress((void**)&Kp,  g_Kp);
    cudaGetSymbolAddress((void**)&Vt,  g_Vt);
    cudaGetSymbolAddress((void**)&Hb,  g_Hb);

    cudaFuncSetAttribute(gemm_hs, cudaFuncAttributeMaxDynamicSharedMemorySize, GH_SMEM);
    cudaFuncSetAttribute(attn_hs, cudaFuncAttributeMaxDynamicSharedMemorySize, AH_SMEM);

    // 0. convert inputs + weights to fp16 (single launch)
    {
        dim3 gC(MTOT*HID/4/256, 7);
        tohalf_all<<<gC, 256>>>(q, k, v, wq, wk, wv, wo,
                                qh, kh, vh, wqh, wkh, wvh, woh);
    }

    // 1. fused QKV projections (z: 0=Q scaled, 1=K, 2=V transposed per-head)
    dim3 gQKV(HID/128, MTOT/128, 3);
    gemm_hs<<<gQKV, 256, GH_SMEM>>>(qh, kh, vh, wqh, wkh, wvh, bq, bk, bv,
                                    Qp, Kp, Vt, -1);

    // 2. attention
    dim3 gF(SEQ/128, BATCH*NHEADS);
    attn_hs<<<gF, 256, AH_SMEM>>>(Qp, Kp, Vt, mask, Hb);

    // 3. output projection (fp32 out)
    dim3 gO(HID/128, MTOT/128, 1);
    gemm_hs<<<gO, 256, GH_SMEM>>>(Hb, Hb, Hb, woh, woh, woh, bo, bo, bo,
                                  out, out, out, 3);
}

// round 10
// speedup vs baseline: 6.7519x; 1.0919x over previous
#include <cuda_runtime.h>
#include <cuda_fp16.h>
#include <cstdint>

#define HID 1024
#define SEQ 2048
#define BATCH 4
#define NHEADS 16
#define DH 64
#define MTOT (BATCH*SEQ)

// ---------------- scratch (static device arrays are allowed) ---------------
__device__ __half g_qh[MTOT*HID];
__device__ __half g_kh[MTOT*HID];
__device__ __half g_vh[MTOT*HID];
__device__ __half g_wqh[HID*HID];
__device__ __half g_wkh[HID*HID];
__device__ __half g_wvh[HID*HID];
__device__ __half g_woh[HID*HID];
__device__ __half g_Qp[MTOT*HID];
__device__ __half g_Kp[MTOT*HID];
__device__ __half g_Vt[BATCH*NHEADS*DH*SEQ];   // [b,h,d,s]
__device__ __half g_Hb[MTOT*HID];

// ---------------- helpers ---------------------------------------------------
__device__ __forceinline__ uint32_t smem_u32(const void* p){
    uint32_t a;
    asm("{ .reg .u64 t; cvta.to.shared.u64 t, %1; cvt.u32.u64 %0, t; }":"=r"(a):"l"(p));
    return a;
}
__device__ __forceinline__ void cp16(const void* dst, const void* src){
    asm volatile("cp.async.cg.shared.global [%0], [%1], 16;"
                 ::"r"(smem_u32(dst)),"l"(src));
}
#define CP_COMMIT() asm volatile("cp.async.commit_group;":::"memory")
#define CP_WAIT1()  asm volatile("cp.async.wait_group 1;":::"memory")
#define CP_WAIT0()  asm volatile("cp.async.wait_group 0;":::"memory")

// mma.sync m16n8k16 fp16 (sm_75+, legal on plain sm_103 target)
__device__ __forceinline__ void mma16(float* d, const uint32_t* a,
                                      uint32_t b0, uint32_t b1){
    asm volatile(
        "mma.sync.aligned.m16n8k16.row.col.f32.f16.f16.f32 "
        "{%0,%1,%2,%3}, {%4,%5,%6,%7}, {%8,%9}, {%0,%1,%2,%3};"
        : "+f"(d[0]),"+f"(d[1]),"+f"(d[2]),"+f"(d[3])
        : "r"(a[0]),"r"(a[1]),"r"(a[2]),"r"(a[3]),
          "r"(b0),"r"(b1));
}
// ldmatrix x4 (sm_75+)
__device__ __forceinline__ void ldm4(uint32_t* r, const void* p){
    asm volatile("ldmatrix.sync.aligned.m8n8.x4.shared.b16 {%0,%1,%2,%3}, [%4];"
        : "=r"(r[0]),"=r"(r[1]),"=r"(r[2]),"=r"(r[3]) : "r"(smem_u32(p)));
}
__device__ __forceinline__ uint32_t packh2(float x, float y){
    __half2 h = __floats2half2_rn(x, y);
    return *(uint32_t*)&h;
}

// ---------------- fused fp32 -> fp16 conversions (one launch) ---------------
__global__ void tohalf_all(
    const float* __restrict__ q, const float* __restrict__ k, const float* __restrict__ v,
    const float* __restrict__ wq, const float* __restrict__ wk,
    const float* __restrict__ wv, const float* __restrict__ wo,
    __half* __restrict__ qh, __half* __restrict__ kh, __half* __restrict__ vh,
    __half* __restrict__ wqh, __half* __restrict__ wkh,
    __half* __restrict__ wvh, __half* __restrict__ woh)
{
    const int which = blockIdx.y;
    const float* s; __half* d; int n4;
    switch(which){
        case 0: s=q;  d=qh;  n4=MTOT*HID/4; break;
        case 1: s=k;  d=kh;  n4=MTOT*HID/4; break;
        case 2: s=v;  d=vh;  n4=MTOT*HID/4; break;
        case 3: s=wq; d=wqh; n4=HID*HID/4;  break;
        case 4: s=wk; d=wkh; n4=HID*HID/4;  break;
        case 5: s=wv; d=wvh; n4=HID*HID/4;  break;
        default:s=wo; d=woh; n4=HID*HID/4;  break;
    }
    int i = blockIdx.x*256 + threadIdx.x;
    if(i < n4){
        float4 vv = ((const float4*)s)[i];
        __half2* o = (__half2*)d + 2*i;
        o[0] = __floats2half2_rn(vv.x, vv.y);
        o[1] = __floats2half2_rn(vv.z, vv.w);
    }
}

// ---------------- warp-MMA GEMM: C = A @ W^T + bias (fp16 in, fp32 acc) -----
// Block 128x128, 8 warps (4x2), warp tile 32x64. K chunks of 64, double buffer.
// 2 CTAs/SM for latency hiding.
// modes: 0=Q(bias,*0.125,half) 1=K(half) 2=V(half, per-head transpose) 3=float
#define GH_SMEM (4*128*72*2)
__global__ __launch_bounds__(256,2) void gemm_hs(
    const __half* __restrict__ A0, const __half* __restrict__ A1, const __half* __restrict__ A2,
    const __half* __restrict__ W0, const __half* __restrict__ W1, const __half* __restrict__ W2,
    const float* __restrict__ b0, const float* __restrict__ b1, const float* __restrict__ b2,
    void* __restrict__ C0, void* __restrict__ C1, void* __restrict__ C2,
    int mode_in)
{
    extern __shared__ __half smh[];
    const int z = blockIdx.z;
    const __half* A    = (z==0)?A0:(z==1)?A1:A2;
    const __half* W    = (z==0)?W0:(z==1)?W1:W2;
    const float*  bias = (z==0)?b0:(z==1)?b1:b2;
    void*         C    = (z==0)?C0:(z==1)?C1:C2;
    const int mode = (mode_in < 0) ? z : mode_in;

    __half* As[2] = { smh,            smh + 128*72 };
    __half* Ws[2] = { smh + 2*128*72, smh + 3*128*72 };

    const int t    = threadIdx.x;
    const int w    = t >> 5;
    const int lane = t & 31;
    const int g    = lane >> 2;
    const int tig  = lane & 3;
    const int wm   = (w >> 1) * 32;
    const int wn   = (w & 1) * 64;
    const int m0   = blockIdx.y * 128;
    const int n0   = blockIdx.x * 128;

    // ldmatrix lane->address components
    const int aRow = wm + (lane & 15);
    const int aCol = (lane >> 4) * 8;
    const int bRow = wn + ((lane >> 4) & 1) * 8 + (lane & 7);
    const int bCol = ((lane >> 3) & 1) * 8;

    float acc[2][8][4];
#pragma unroll
    for(int mt=0;mt<2;mt++)
#pragma unroll
        for(int nt=0;nt<8;nt++)
#pragma unroll
            for(int i2=0;i2<4;i2++) acc[mt][nt][i2]=0.f;

    // prologue: chunk 0
#pragma unroll
    for(int i=0;i<4;i++){
        int s = t + 256*i; int r = s>>3, c8 = s&7;
        cp16(&As[0][r*72 + c8*8], A + (size_t)(m0+r)*HID + c8*8);
        cp16(&Ws[0][r*72 + c8*8], W + (size_t)(n0+r)*HID + c8*8);
    }
    CP_COMMIT();

    for(int c=0;c<16;c++){
        const int buf = c & 1;
        if(c+1 < 16){
            const int k0 = (c+1)*64, nb = (c+1)&1;
#pragma unroll
            for(int i=0;i<4;i++){
                int s = t + 256*i; int r = s>>3, c8 = s&7;
                cp16(&As[nb][r*72 + c8*8], A + (size_t)(m0+r)*HID + k0 + c8*8);
                cp16(&Ws[nb][r*72 + c8*8], W + (size_t)(n0+r)*HID + k0 + c8*8);
            }
            CP_COMMIT();
            CP_WAIT1();
        } else {
            CP_WAIT0();
        }
        __syncthreads();

        const __half* aBase = &As[buf][aRow*72 + aCol];
        const __half* bBase = &Ws[buf][bRow*72 + bCol];
#pragma unroll
        for(int k16=0;k16<4;k16++){
            const int kk = k16*16;
            uint32_t a[2][4];
            ldm4(a[0], aBase + kk);
            ldm4(a[1], aBase + 16*72 + kk);
#pragma unroll
            for(int p=0;p<4;p++){
                uint32_t bb[4];
                ldm4(bb, bBase + p*16*72 + kk);
#pragma unroll
                for(int mt=0;mt<2;mt++){
                    mma16(acc[mt][2*p],   a[mt], bb[0], bb[1]);
                    mma16(acc[mt][2*p+1], a[mt], bb[2], bb[3]);
                }
            }
        }
        __syncthreads();
    }

    // epilogue
#pragma unroll
    for(int mt=0;mt<2;mt++){
        const int row0 = m0 + wm + mt*16 + g;
        const int row1 = row0 + 8;
#pragma unroll
        for(int nt=0;nt<8;nt++){
            const int col0 = n0 + wn + nt*8 + 2*tig;
            const float bb0 = bias[col0], bb1 = bias[col0+1];
            float v00 = acc[mt][nt][0] + bb0, v01 = acc[mt][nt][1] + bb1;
            float v10 = acc[mt][nt][2] + bb0, v11 = acc[mt][nt][3] + bb1;
            if(mode==0){ v00*=0.125f; v01*=0.125f; v10*=0.125f; v11*=0.125f; }
            if(mode==2){
                __half* Ch = (__half*)C;
                const int bb = row0 >> 11;
                const int s0 = row0 & 2047, s1 = row1 & 2047;
                const int h0 = col0 >> 6,  d0 = col0 & 63;
                const int h1 = (col0+1) >> 6, d1 = (col0+1) & 63;
                Ch[((size_t)(bb*NHEADS+h0)*DH + d0)*SEQ + s0] = __float2half_rn(v00);
                Ch[((size_t)(bb*NHEADS+h1)*DH + d1)*SEQ + s0] = __float2half_rn(v01);
                Ch[((size_t)(bb*NHEADS+h0)*DH + d0)*SEQ + s1] = __float2half_rn(v10);
                Ch[((size_t)(bb*NHEADS+h1)*DH + d1)*SEQ + s1] = __float2half_rn(v11);
            } else if(mode==3){
                float* Cf = (float*)C;
                *(float2*)&Cf[(size_t)row0*HID + col0] = make_float2(v00, v01);
                *(float2*)&Cf[(size_t)row1*HID + col0] = make_float2(v10, v11);
            } else {
                __half* Ch = (__half*)C;
                *(__half2*)&Ch[(size_t)row0*HID + col0] = __floats2half2_rn(v00, v01);
                *(__half2*)&Ch[(size_t)row1*HID + col0] = __floats2half2_rn(v10, v11);
            }
        }
    }
}

// ---------------- warp-MMA attention (fp16, P in regs, 2 CTAs/SM) -----------
// CTA = one (b,h) x 128 queries; 8 warps x 16 rows. 128-key tiles, K/V dbl-buf.
// S computed in two 64-key halves to keep registers under 128 -> occupancy 2.
#define AH_SMEM ((128*72 + 2*128*72 + 2*64*136)*2)
__global__ __launch_bounds__(256,2) void attn_hs(
    const __half* __restrict__ Qp, const __half* __restrict__ Kp,
    const __half* __restrict__ Vt, const int* __restrict__ mask,
    __half* __restrict__ Hb)
{
    extern __shared__ __half smh[];
    __half* Qs    = smh;                       // [128][72]
    __half* Ks[2] = { smh + 128*72, smh + 2*128*72 };
    __half* Vs[2] = { smh + 3*128*72, smh + 3*128*72 + 64*136 };

    const int t    = threadIdx.x;
    const int w    = t >> 5;
    const int lane = t & 31;
    const int g    = lane >> 2;
    const int tig  = lane & 3;
    const int bh = blockIdx.y;
    const int b  = bh >> 4, h = bh & 15;
    const int q0 = blockIdx.x * 128;

    // ldmatrix lane->address components
    const int aRow = w*16 + (lane & 15);                  // A-role rows (Q)
    const int aCol = (lane >> 4) * 8;
    const int bRow = ((lane >> 4) & 1) * 8 + (lane & 7);  // B-role rows (K, V)
    const int bCol = ((lane >> 3) & 1) * 8;

    // load Q tile + K/V tile 0 in one group
#pragma unroll
    for(int i=0;i<4;i++){
        int s = t + 256*i; int r = s>>3, c8 = s&7;
        cp16(&Qs[r*72 + c8*8], Qp + (size_t)(b*SEQ + q0 + r)*HID + h*DH + c8*8);
        cp16(&Ks[0][r*72 + c8*8], Kp + (size_t)(b*SEQ + r)*HID + h*DH + c8*8);
    }
#pragma unroll
    for(int i=0;i<4;i++){
        int s = t + 256*i; int d = s>>4, c8 = s&15;
        cp16(&Vs[0][d*136 + c8*8], Vt + ((size_t)(b*NHEADS+h)*DH + d)*SEQ + c8*8);
    }
    CP_COMMIT();

    const int row0g = q0 + w*16 + g;
    const int m0v = mask[b*SEQ + row0g];
    const int m1v = mask[b*SEQ + row0g + 8];

    float o[8][4];
#pragma unroll
    for(int nt=0;nt<8;nt++)
#pragma unroll
        for(int i2=0;i2<4;i2++) o[nt][i2]=0.f;
    float lsum0 = 0.f, lsum1 = 0.f;

    uint32_t aq[4][4];

    for(int kt=0; kt<16; kt++){
        const int buf = kt & 1;
        if(kt+1 < 16){
            const int nb = buf ^ 1;
            const size_t krow = (size_t)(b*SEQ + (kt+1)*128);
#pragma unroll
            for(int i=0;i<4;i++){
                int s = t + 256*i; int r = s>>3, c8 = s&7;
                cp16(&Ks[nb][r*72 + c8*8], Kp + (krow + r)*HID + h*DH + c8*8);
            }
#pragma unroll
            for(int i=0;i<4;i++){
                int s = t + 256*i; int d = s>>4, c8 = s&15;
                cp16(&Vs[nb][d*136 + c8*8],
                     Vt + ((size_t)(b*NHEADS+h)*DH + d)*SEQ + (kt+1)*128 + c8*8);
            }
            CP_COMMIT();
            CP_WAIT1();
        } else {
            CP_WAIT0();
        }
        __syncthreads();

        if(kt==0){
            const __half* qBase = &Qs[aRow*72 + aCol];
#pragma unroll
            for(int k16=0;k16<4;k16++) ldm4(aq[k16], qBase + k16*16);
        }

        // process the 128-key tile as two 64-key halves (keeps s4 at 32 regs)
#pragma unroll
        for(int half=0; half<2; half++){
            // S = Q @ K^T for 64 keys (Q carries 1/8); warp computes 16x64
            float s4[8][4];
#pragma unroll
            for(int nt=0;nt<8;nt++)
#pragma unroll
                for(int i2=0;i2<4;i2++) s4[nt][i2]=0.f;
            const __half* kBase = &Ks[buf][(half*64 + bRow)*72 + bCol];
#pragma unroll
            for(int k16=0;k16<4;k16++){
                const int kk = k16*16;
#pragma unroll
                for(int p=0;p<4;p++){
                    uint32_t bb[4];
                    ldm4(bb, kBase + p*16*72 + kk);
                    mma16(s4[2*p],   aq[k16], bb[0], bb[1]);
                    mma16(s4[2*p+1], aq[k16], bb[2], bb[3]);
                }
            }

            // O += exp(S) @ V for these 64 keys (4 PV k-steps)
            const __half* vBase = &Vs[buf][bRow*136 + bCol + half*64];
#pragma unroll
            for(int k16=0;k16<4;k16++){
                float p00,p01,p02,p03, p10,p11,p12,p13;
                if(m0v){
                    p00 = __expf(s4[2*k16][0]);   p01 = __expf(s4[2*k16][1]);
                    p02 = __expf(s4[2*k16+1][0]); p03 = __expf(s4[2*k16+1][1]);
                } else { p00=p01=p02=p03=1.f; }
                if(m1v){
                    p10 = __expf(s4[2*k16][2]);   p11 = __expf(s4[2*k16][3]);
                    p12 = __expf(s4[2*k16+1][2]); p13 = __expf(s4[2*k16+1][3]);
                } else { p10=p11=p12=p13=1.f; }
                lsum0 += p00 + p01 + p02 + p03;
                lsum1 += p10 + p11 + p12 + p13;
                uint32_t ap[4];
                ap[0] = packh2(p00, p01);
                ap[1] = packh2(p10, p11);
                ap[2] = packh2(p02, p03);
                ap[3] = packh2(p12, p13);
                const int kk = k16*16;
#pragma unroll
                for(int p=0;p<4;p++){
                    uint32_t bb[4];
                    ldm4(bb, vBase + p*16*136 + kk);
                    mma16(o[2*p],   ap, bb[0], bb[1]);
                    mma16(o[2*p+1], ap, bb[2], bb[3]);
                }
            }
        }
        __syncthreads();
    }

    // reduce row sums across the lane quad
    lsum0 += __shfl_xor_sync(0xffffffffu, lsum0, 1);
    lsum0 += __shfl_xor_sync(0xffffffffu, lsum0, 2);
    lsum1 += __shfl_xor_sync(0xffffffffu, lsum1, 1);
    lsum1 += __shfl_xor_sync(0xffffffffu, lsum1, 2);
    const float inv0 = 1.f / lsum0;
    const float inv1 = 1.f / lsum1;

    // write O (fp16: feeds the output projection)
    const size_t r0 = (size_t)(b*SEQ + row0g)*HID + h*DH;
    const size_t r1 = r0 + 8*HID;
#pragma unroll
    for(int nt=0;nt<8;nt++){
        const int cc = nt*8 + 2*tig;
        *(__half2*)&Hb[r0 + cc] = __floats2half2_rn(o[nt][0]*inv0, o[nt][1]*inv0);
        *(__half2*)&Hb[r1 + cc] = __floats2half2_rn(o[nt][2]*inv1, o[nt][3]*inv1);
    }
}

// ---------------------------------------------------------------------------

extern "C" void kernel_launch(void* const* d_in, const int* in_sizes, int n_in,
                              void* d_out, int out_size)
{
    const float* q    = (const float*)d_in[0];
    const float* k    = (const float*)d_in[1];
    const float* v    = (const float*)d_in[2];
    const int*   mask = (const int*)  d_in[3];
    const float* wq   = (const float*)d_in[4];
    const float* bq   = (const float*)d_in[5];
    const float* wk   = (const float*)d_in[6];
    const float* bk   = (const float*)d_in[7];
    const float* wv   = (const float*)d_in[8];
    const float* bv   = (const float*)d_in[9];
    const float* wo   = (const float*)d_in[10];
    const float* bo   = (const float*)d_in[11];
    float* out = (float*)d_out;

    __half *qh,*kh,*vh,*wqh,*wkh,*wvh,*woh,*Qp,*Kp,*Vt,*Hb;
    cudaGetSymbolAddress((void**)&qh,  g_qh);
    cudaGetSymbolAddress((void**)&kh,  g_kh);
    cudaGetSymbolAddress((void**)&vh,  g_vh);
    cudaGetSymbolAddress((void**)&wqh, g_wqh);
    cudaGetSymbolAddress((void**)&wkh, g_wkh);
    cudaGetSymbolAddress((void**)&wvh, g_wvh);
    cudaGetSymbolAddress((void**)&woh, g_woh);
    cudaGetSymbolAddress((void**)&Qp,  g_Qp);
    cudaGetSymbolAddress((void**)&Kp,  g_Kp);
    cudaGetSymbolAddress((void**)&Vt,  g_Vt);
    cudaGetSymbolAddress((void**)&Hb,  g_Hb);

    cudaFuncSetAttribute(gemm_hs, cudaFuncAttributeMaxDynamicSharedMemorySize, GH_SMEM);
    cudaFuncSetAttribute(attn_hs, cudaFuncAttributeMaxDynamicSharedMemorySize, AH_SMEM);

    // 0. convert inputs + weights to fp16 (single launch)
    {
        dim3 gC(MTOT*HID/4/256, 7);
        tohalf_all<<<gC, 256>>>(q, k, v, wq, wk, wv, wo,
                                qh, kh, vh, wqh, wkh, wvh, woh);
    }

    // 1. fused QKV projections (z: 0=Q scaled, 1=K, 2=V transposed per-head)
    dim3 gQKV(HID/128, MTOT/128, 3);
    gemm_hs<<<gQKV, 256, GH_SMEM>>>(qh, kh, vh, wqh, wkh, wvh, bq, bk, bv,
                                    Qp, Kp, Vt, -1);

    // 2. attention
    dim3 gF(SEQ/128, BATCH*NHEADS);
    attn_hs<<<gF, 256, AH_SMEM>>>(Qp, Kp, Vt, mask, Hb);

    // 3. output projection (fp32 out)
    dim3 gO(HID/128, MTOT/128, 1);
    gemm_hs<<<gO, 256, GH_SMEM>>>(Hb, Hb, Hb, woh, woh, woh, bo, bo, bo,
                                  out, out, out, 3);
}